// round 1
// baseline (speedup 1.0000x reference)
#include <cuda_runtime.h>

// SwinStyleAttention: B=8, C=128, H=W=256, window 8x8, shift 4, 4 heads, dh=32.
// Fully fused: one CTA per window (8192 CTAs), all intermediates in SMEM.
// fp32 baseline (correctness anchor); next rounds move GEMMs to tcgen05.

#define B_    8
#define C_    128
#define H_    256
#define W_    256
#define SS_   4
#define L_    64          // tokens per window (8x8)
#define NC_   384         // 3 * heads * dh
#define DH_   32
#define SCALE_ 0.17677669529663687f   // 32^-0.5

// smem layout (floats):
//   xs   [64*129]  = 8256   (input tile, token-major padded; reused as swizzled fin[128][64])
//   wbuf [16384]             (w_qkv 32-row chunk = 12288 used; w_proj full = 16384 used)
//   qkvs [64*384]  = 24576   (qkv; q-region overwritten by attention output O)
#define XS_OFF   0
#define WB_OFF   8256
#define QK_OFF   (8256 + 16384)
#define SMEM_FLOATS (8256 + 16384 + 24576)

__global__ __launch_bounds__(256, 1)
void swin_fused_kernel(const float* __restrict__ x,
                       const float* __restrict__ w_qkv,
                       const float* __restrict__ w_proj,
                       const float* __restrict__ b_proj,
                       float* __restrict__ out)
{
    extern __shared__ float smem[];
    float* xs   = smem + XS_OFF;
    float* wbuf = smem + WB_OFF;
    float* qkvs = smem + QK_OFF;

    const int tid  = threadIdx.x;
    const int lane = tid & 31;
    const int tg   = tid >> 5;       // warp id 0..7

    const int win = blockIdx.x;      // 8192 windows
    const int b   = win >> 10;       // 1024 windows per batch (32x32)
    const int wy  = (win >> 5) & 31;
    const int wx  = win & 31;
    const int hbase = wy * 8 + SS_;  // shifted-frame -> original-frame offset (+4 mod 256)
    const int wbase = wx * 8 + SS_;

    // ================= Phase 0: load rolled window tile -> xs[t*129 + c] =================
    for (int i = tid; i < L_ * C_; i += 256) {
        int c = i >> 6, t = i & 63;
        int h = (hbase + (t >> 3)) & 255;
        int w = (wbase + (t & 7)) & 255;
        xs[t * 129 + c] = x[(((b * C_ + c) * H_) + h) * W_ + w];
    }
    __syncthreads();

    // ================= Phase 1: qkv = x @ w_qkv  (64x384, K=128) =================
    // thread (tg, lane): 8 tokens (tg*8+i) x 12 cols (lane+32j)
    float acc[8][12];
    #pragma unroll
    for (int i = 0; i < 8; i++)
        #pragma unroll
        for (int j = 0; j < 12; j++) acc[i][j] = 0.f;

    for (int kb = 0; kb < C_; kb += 32) {
        for (int i = tid; i < 32 * NC_; i += 256)
            wbuf[i] = w_qkv[kb * NC_ + i];
        __syncthreads();
        #pragma unroll 2
        for (int kk = 0; kk < 32; kk++) {
            float xr[8], wr[12];
            #pragma unroll
            for (int i = 0; i < 8; i++) xr[i] = xs[(tg * 8 + i) * 129 + kb + kk];
            #pragma unroll
            for (int j = 0; j < 12; j++) wr[j] = wbuf[kk * NC_ + lane + 32 * j];
            #pragma unroll
            for (int i = 0; i < 8; i++)
                #pragma unroll
                for (int j = 0; j < 12; j++)
                    acc[i][j] = fmaf(xr[i], wr[j], acc[i][j]);
        }
        __syncthreads();
    }
    #pragma unroll
    for (int i = 0; i < 8; i++)
        #pragma unroll
        for (int j = 0; j < 12; j++)
            qkvs[(tg * 8 + i) * NC_ + lane + 32 * j] = acc[i][j];
    __syncthreads();

    // ================= Phase 2: attention (+ overlap: preload w_proj into wbuf) =========
    for (int i = tid; i < C_ * C_; i += 256)
        wbuf[i] = w_proj[i];

    {
        const int head = tg >> 1;                 // 2 warps per head
        const int r    = ((tg & 1) << 5) + lane;  // this lane's token row
        const int qoff = head * DH_;

        float qv[32];
        #pragma unroll
        for (int d4 = 0; d4 < 8; d4++) {
            float4 t4 = *(const float4*)&qkvs[r * NC_ + qoff + 4 * d4];
            qv[4*d4+0] = t4.x; qv[4*d4+1] = t4.y; qv[4*d4+2] = t4.z; qv[4*d4+3] = t4.w;
        }

        float s[64];
        float mx = -1e30f;
        #pragma unroll
        for (int j = 0; j < 64; j++) {
            float sum = 0.f;
            const float4* kp = (const float4*)&qkvs[j * NC_ + 128 + qoff];
            #pragma unroll
            for (int d4 = 0; d4 < 8; d4++) {
                float4 kv = kp[d4];
                sum = fmaf(qv[4*d4+0], kv.x, sum);
                sum = fmaf(qv[4*d4+1], kv.y, sum);
                sum = fmaf(qv[4*d4+2], kv.z, sum);
                sum = fmaf(qv[4*d4+3], kv.w, sum);
            }
            s[j] = sum * SCALE_;
            mx = fmaxf(mx, s[j]);
        }
        float denom = 0.f;
        #pragma unroll
        for (int j = 0; j < 64; j++) {
            s[j] = __expf(s[j] - mx);
            denom += s[j];
        }
        const float inv = 1.f / denom;

        float o[32];
        #pragma unroll
        for (int d = 0; d < 32; d++) o[d] = 0.f;
        #pragma unroll
        for (int j = 0; j < 64; j++) {
            float p = s[j] * inv;
            const float4* vp = (const float4*)&qkvs[j * NC_ + 256 + qoff];
            #pragma unroll
            for (int d4 = 0; d4 < 8; d4++) {
                float4 vv = vp[d4];
                o[4*d4+0] = fmaf(p, vv.x, o[4*d4+0]);
                o[4*d4+1] = fmaf(p, vv.y, o[4*d4+1]);
                o[4*d4+2] = fmaf(p, vv.z, o[4*d4+2]);
                o[4*d4+3] = fmaf(p, vv.w, o[4*d4+3]);
            }
        }
        // write O over the q region (cols 0..127); row/col disjoint across warps
        #pragma unroll
        for (int d4 = 0; d4 < 8; d4++) {
            *(float4*)&qkvs[r * NC_ + qoff + 4 * d4] =
                make_float4(o[4*d4+0], o[4*d4+1], o[4*d4+2], o[4*d4+3]);
        }
    }
    __syncthreads();

    // ================= Phase 3: proj = O @ w_proj + b  (64x128, K=128) ==================
    float acc2[8][4];
    #pragma unroll
    for (int i = 0; i < 8; i++)
        #pragma unroll
        for (int j = 0; j < 4; j++) acc2[i][j] = 0.f;

    #pragma unroll 4
    for (int k = 0; k < 128; k++) {
        float xr[8], wr[4];
        #pragma unroll
        for (int i = 0; i < 8; i++) xr[i] = qkvs[(tg * 8 + i) * NC_ + k];
        #pragma unroll
        for (int j = 0; j < 4; j++) wr[j] = wbuf[k * 128 + lane + 32 * j];
        #pragma unroll
        for (int i = 0; i < 8; i++)
            #pragma unroll
            for (int j = 0; j < 4; j++)
                acc2[i][j] = fmaf(xr[i], wr[j], acc2[i][j]);
    }

    float bias[4];
    #pragma unroll
    for (int j = 0; j < 4; j++) bias[j] = b_proj[lane + 32 * j];

    // stage result into xs as swizzled fin[c][t]: conflict-free on both write and read
    #pragma unroll
    for (int i = 0; i < 8; i++) {
        int t = tg * 8 + i;
        #pragma unroll
        for (int j = 0; j < 4; j++) {
            int c = lane + 32 * j;
            xs[c * 64 + (t ^ (c & 31))] = acc2[i][j] + bias[j];
        }
    }
    __syncthreads();

    // ================= Phase 4: coalesced scatter to [B,C,H,W] with reverse roll =========
    for (int i = tid; i < L_ * C_; i += 256) {
        int c = i >> 6, t = i & 63;
        int h = (hbase + (t >> 3)) & 255;
        int w = (wbase + (t & 7)) & 255;
        out[(((b * C_ + c) * H_) + h) * W_ + w] = xs[c * 64 + (t ^ (c & 31))];
    }
}

extern "C" void kernel_launch(void* const* d_in, const int* in_sizes, int n_in,
                              void* d_out, int out_size)
{
    const float* x      = (const float*)d_in[0];
    const float* w_qkv  = (const float*)d_in[1];
    const float* w_proj = (const float*)d_in[2];
    const float* b_proj = (const float*)d_in[3];
    float* out = (float*)d_out;

    const size_t smem_bytes = (size_t)SMEM_FLOATS * sizeof(float);  // 196864 B
    cudaFuncSetAttribute(swin_fused_kernel,
                         cudaFuncAttributeMaxDynamicSharedMemorySize,
                         (int)smem_bytes);
    swin_fused_kernel<<<8192, 256, smem_bytes>>>(x, w_qkv, w_proj, b_proj, out);
}

// round 3
// speedup vs baseline: 2.0762x; 2.0762x over previous
#include <cuda_runtime.h>
#include <cuda_bf16.h>
#include <cstdint>

// SwinStyleAttention via mma.sync bf16 hi/lo (HMMA path; tcgen05 PTX rejected by
// harness virtual arch compute_103). 1 CTA = 1 window (M=64), 256 threads.

#define KPAD   136                    // padded row stride (bf16 elems); 272B: ldmatrix conflict-free
#define ROWB   (KPAD * 2)             // 272 bytes
#define PLANE  (64 * ROWB)            // 17408 B  [64][136] bf16
#define WPLANE (128 * ROWB)           // 34816 B  [128][136] bf16
#define XHI    0
#define XLO    PLANE
#define YBASE  (2 * PLANE)            // q_hi,q_lo,k_hi,k_lo,v_hi,v_lo planes
#define WBASE  (YBASE + 6 * PLANE)    // 139264: W hi plane + lo plane
#define BIASO  (WBASE + 2 * WPLANE)   // 208896
#define FINO   YBASE                  // f32 [128][64] overlay (Y dead by then)
#define SMEM_BYTES (BIASO + 512)
#define SCALE_ 0.17677669529663687f

// Pre-transposed, hi/lo-split weights: g_wq[nc][part][n*KPAD+k] = split(wqkv[k*384+nc*128+n])
__device__ __nv_bfloat16 g_wq[3][2][128 * KPAD];
__device__ __nv_bfloat16 g_wp[2][128 * KPAD];

static __device__ __forceinline__ uint32_t smem_u32(const void* p) {
    uint32_t a;
    asm("{ .reg .u64 t; cvta.to.shared.u64 t, %1; cvt.u32.u64 %0, t; }" : "=r"(a) : "l"(p));
    return a;
}

#define LDSM4(R0, R1, R2, R3, ADDR) \
    asm volatile("ldmatrix.sync.aligned.m8n8.x4.shared.b16 {%0,%1,%2,%3}, [%4];" \
                 : "=r"(R0), "=r"(R1), "=r"(R2), "=r"(R3) : "r"(ADDR))
#define LDSM4T(R0, R1, R2, R3, ADDR) \
    asm volatile("ldmatrix.sync.aligned.m8n8.x4.trans.shared.b16 {%0,%1,%2,%3}, [%4];" \
                 : "=r"(R0), "=r"(R1), "=r"(R2), "=r"(R3) : "r"(ADDR))
#define MMA(D, A, B) \
    asm volatile("mma.sync.aligned.m16n8k16.row.col.f32.bf16.bf16.f32 " \
                 "{%0,%1,%2,%3},{%4,%5,%6,%7},{%8,%9},{%0,%1,%2,%3};" \
                 : "+f"((D)[0]), "+f"((D)[1]), "+f"((D)[2]), "+f"((D)[3]) \
                 : "r"((A)[0]), "r"((A)[1]), "r"((A)[2]), "r"((A)[3]), \
                   "r"((B)[0]), "r"((B)[1]))

// split two floats into packed bf16x2 hi and lo residual
static __device__ __forceinline__ void split2(float x, float y, uint32_t& hi, uint32_t& lo) {
    __nv_bfloat16 hx = __float2bfloat16(x), hy = __float2bfloat16(y);
    __nv_bfloat16 lx = __float2bfloat16(x - __bfloat162float(hx));
    __nv_bfloat16 ly = __float2bfloat16(y - __bfloat162float(hy));
    hi = (uint32_t)__bfloat16_as_ushort(hx) | ((uint32_t)__bfloat16_as_ushort(hy) << 16);
    lo = (uint32_t)__bfloat16_as_ushort(lx) | ((uint32_t)__bfloat16_as_ushort(ly) << 16);
}

// ---------------- prep: transpose + hi/lo split weights ----------------
__global__ void prep_weights(const float* __restrict__ wqkv, const float* __restrict__ wproj) {
    int i = blockIdx.x * blockDim.x + threadIdx.x;
    if (i < 3 * 128 * KPAD) {
        int k = i % KPAD, n = (i / KPAD) & 127, nc = i / (KPAD * 128);
        float v = (k < 128) ? wqkv[k * 384 + nc * 128 + n] : 0.f;
        __nv_bfloat16 h = __float2bfloat16(v);
        g_wq[nc][0][n * KPAD + k] = h;
        g_wq[nc][1][n * KPAD + k] = __float2bfloat16(v - __bfloat162float(h));
    } else if (i < 3 * 128 * KPAD + 128 * KPAD) {
        int j = i - 3 * 128 * KPAD;
        int k = j % KPAD, n = j / KPAD;
        float v = (k < 128) ? wproj[k * 128 + n] : 0.f;
        __nv_bfloat16 h = __float2bfloat16(v);
        g_wp[0][n * KPAD + k] = h;
        g_wp[1][n * KPAD + k] = __float2bfloat16(v - __bfloat162float(h));
    }
}

// ---------------- main fused kernel ----------------
__global__ __launch_bounds__(256, 1)
void swin_mma_kernel(const float* __restrict__ x,
                     const float* __restrict__ b_proj,
                     float* __restrict__ out)
{
    extern __shared__ __align__(16) unsigned char smem[];
    const uint32_t sb = smem_u32(smem);

    const int tid = threadIdx.x;
    const int lane = tid & 31;
    const int warp = tid >> 5;
    const int g = lane >> 2;       // row-in-tile group
    const int t4 = lane & 3;

    const int win = blockIdx.x;
    const int b = win >> 10, wy = (win >> 5) & 31, wx = win & 31;
    const int hbase = wy * 8 + 4, wbase = wx * 8 + 4;

    // ---- phase 0: bias + rolled-window gather, split into x hi/lo planes ----
    if (tid < 128) ((float*)(smem + BIASO))[tid] = b_proj[tid];
    for (int i = tid; i < 64 * 128; i += 256) {
        int c = i >> 6, t = i & 63;
        int h = (hbase + (t >> 3)) & 255;
        int w = (wbase + (t & 7)) & 255;
        float v = x[(((b * 128 + c) * 256) + h) * 256 + w];
        __nv_bfloat16 hv = __float2bfloat16(v);
        *(__nv_bfloat16*)(smem + XHI + t * ROWB + c * 2) = hv;
        *(__nv_bfloat16*)(smem + XLO + t * ROWB + c * 2) =
            __float2bfloat16(v - __bfloat162float(hv));
    }

    // ---- phase 1: qkv = x @ Wqkv, 3 N-chunks of 128 (q, k, v) ----
    {
        const int mbase = (warp >> 2) * 32;   // 2 M groups
        const int nbase = (warp & 3) * 32;    // 4 N groups
        for (int nc = 0; nc < 3; nc++) {
            __syncthreads();                                    // W buffer free / x ready
            {
                const uint4* src = (const uint4*)(&g_wq[nc][0][0]);
                uint4* dst = (uint4*)(smem + WBASE);
                for (int i = tid; i < (2 * WPLANE) / 16; i += 256) dst[i] = src[i];
            }
            __syncthreads();                                    // W ready

            float acc[2][4][4];
            #pragma unroll
            for (int mt = 0; mt < 2; mt++)
                #pragma unroll
                for (int nt = 0; nt < 4; nt++)
                    #pragma unroll
                    for (int q = 0; q < 4; q++) acc[mt][nt][q] = 0.f;

            #pragma unroll
            for (int p = 0; p < 3; p++) {                       // (h,h),(h,l),(l,h)
                const uint32_t Ab = sb + ((p == 2) ? XLO : XHI);
                const uint32_t Bb = sb + WBASE + ((p == 1) ? WPLANE : 0);
                #pragma unroll
                for (int kt = 0; kt < 8; kt++) {
                    uint32_t a[2][4], bfr[4][2];
                    #pragma unroll
                    for (int mt = 0; mt < 2; mt++) {
                        uint32_t ad = Ab + (mbase + mt * 16 + (lane & 15)) * ROWB
                                         + kt * 32 + (lane >> 4) * 16;
                        LDSM4(a[mt][0], a[mt][1], a[mt][2], a[mt][3], ad);
                    }
                    #pragma unroll
                    for (int ng = 0; ng < 2; ng++) {
                        uint32_t bd = Bb + (nbase + ng * 16 + ((lane >> 4) << 3) + (lane & 7)) * ROWB
                                         + kt * 32 + ((lane >> 3) & 1) * 16;
                        uint32_t r0, r1, r2, r3;
                        LDSM4(r0, r1, r2, r3, bd);
                        bfr[2 * ng][0] = r0; bfr[2 * ng][1] = r1;
                        bfr[2 * ng + 1][0] = r2; bfr[2 * ng + 1][1] = r3;
                    }
                    #pragma unroll
                    for (int mt = 0; mt < 2; mt++)
                        #pragma unroll
                        for (int nt = 0; nt < 4; nt++)
                            MMA(acc[mt][nt], a[mt], bfr[nt]);
                }
            }
            // epilogue: split to Y hi/lo planes (chunk nc)
            unsigned char* Yh = smem + YBASE + nc * 2 * PLANE;
            unsigned char* Yl = Yh + PLANE;
            #pragma unroll
            for (int mt = 0; mt < 2; mt++)
                #pragma unroll
                for (int nt = 0; nt < 4; nt++) {
                    int ch = nbase + nt * 8 + 2 * t4;
                    int tok = mbase + mt * 16 + g;
                    uint32_t hi, lo;
                    split2(acc[mt][nt][0], acc[mt][nt][1], hi, lo);
                    *(uint32_t*)(Yh + tok * ROWB + ch * 2) = hi;
                    *(uint32_t*)(Yl + tok * ROWB + ch * 2) = lo;
                    split2(acc[mt][nt][2], acc[mt][nt][3], hi, lo);
                    *(uint32_t*)(Yh + (tok + 8) * ROWB + ch * 2) = hi;
                    *(uint32_t*)(Yl + (tok + 8) * ROWB + ch * 2) = lo;
                }
        }
    }
    __syncthreads();   // Y complete; x planes now dead -> reuse as O planes

    // ---- phase 2: attention. warp -> (head, 32-row half) ----
    {
        const int head = warp >> 1;
        const int mh = warp & 1;
        const uint32_t Yq = sb + YBASE, Yk = Yq + 2 * PLANE, Yv = Yk + 2 * PLANE;
        const int chB = head * 64;                 // byte offset of head slice

        #pragma unroll
        for (int mt = 0; mt < 2; mt++) {
            const int mbase = mh * 32 + mt * 16;
            float s[8][4];
            #pragma unroll
            for (int nt = 0; nt < 8; nt++)
                #pragma unroll
                for (int q = 0; q < 4; q++) s[nt][q] = 0.f;

            // QK^T
            #pragma unroll
            for (int p = 0; p < 3; p++) {
                const uint32_t Ab = Yq + ((p == 2) ? PLANE : 0);
                const uint32_t Bb = Yk + ((p == 1) ? PLANE : 0);
                #pragma unroll
                for (int kt = 0; kt < 2; kt++) {
                    uint32_t a[4];
                    uint32_t ad = Ab + (mbase + (lane & 15)) * ROWB
                                     + chB + kt * 32 + (lane >> 4) * 16;
                    LDSM4(a[0], a[1], a[2], a[3], ad);
                    #pragma unroll
                    for (int ng = 0; ng < 4; ng++) {
                        uint32_t bd = Bb + (ng * 16 + ((lane >> 4) << 3) + (lane & 7)) * ROWB
                                         + chB + kt * 32 + ((lane >> 3) & 1) * 16;
                        uint32_t r0, r1, r2, r3;
                        LDSM4(r0, r1, r2, r3, bd);
                        uint32_t b0[2] = {r0, r1}, b1[2] = {r2, r3};
                        MMA(s[2 * ng], a, b0);
                        MMA(s[2 * ng + 1], a, b1);
                    }
                }
            }
            // softmax (rows g and g+8; quad lanes share a row)
            float mx0 = -1e30f, mx1 = -1e30f;
            #pragma unroll
            for (int nt = 0; nt < 8; nt++) {
                #pragma unroll
                for (int q = 0; q < 4; q++) s[nt][q] *= SCALE_;
                mx0 = fmaxf(mx0, fmaxf(s[nt][0], s[nt][1]));
                mx1 = fmaxf(mx1, fmaxf(s[nt][2], s[nt][3]));
            }
            mx0 = fmaxf(mx0, __shfl_xor_sync(0xffffffffu, mx0, 1));
            mx0 = fmaxf(mx0, __shfl_xor_sync(0xffffffffu, mx0, 2));
            mx1 = fmaxf(mx1, __shfl_xor_sync(0xffffffffu, mx1, 1));
            mx1 = fmaxf(mx1, __shfl_xor_sync(0xffffffffu, mx1, 2));
            float sm0 = 0.f, sm1 = 0.f;
            #pragma unroll
            for (int nt = 0; nt < 8; nt++) {
                s[nt][0] = __expf(s[nt][0] - mx0); sm0 += s[nt][0];
                s[nt][1] = __expf(s[nt][1] - mx0); sm0 += s[nt][1];
                s[nt][2] = __expf(s[nt][2] - mx1); sm1 += s[nt][2];
                s[nt][3] = __expf(s[nt][3] - mx1); sm1 += s[nt][3];
            }
            sm0 += __shfl_xor_sync(0xffffffffu, sm0, 1);
            sm0 += __shfl_xor_sync(0xffffffffu, sm0, 2);
            sm1 += __shfl_xor_sync(0xffffffffu, sm1, 1);
            sm1 += __shfl_xor_sync(0xffffffffu, sm1, 2);
            const float inv0 = 1.f / sm0, inv1 = 1.f / sm1;

            // P -> A fragments (hi/lo), directly from score regs
            uint32_t pah[4][4], pal[4][4];
            #pragma unroll
            for (int kk = 0; kk < 4; kk++) {
                split2(s[2 * kk][0] * inv0, s[2 * kk][1] * inv0, pah[kk][0], pal[kk][0]);
                split2(s[2 * kk][2] * inv1, s[2 * kk][3] * inv1, pah[kk][1], pal[kk][1]);
                split2(s[2 * kk + 1][0] * inv0, s[2 * kk + 1][1] * inv0, pah[kk][2], pal[kk][2]);
                split2(s[2 * kk + 1][2] * inv1, s[2 * kk + 1][3] * inv1, pah[kk][3], pal[kk][3]);
            }

            // P @ V
            float o[4][4];
            #pragma unroll
            for (int nt = 0; nt < 4; nt++)
                #pragma unroll
                for (int q = 0; q < 4; q++) o[nt][q] = 0.f;
            #pragma unroll
            for (int p = 0; p < 3; p++) {
                const uint32_t Bb = Yv + ((p == 1) ? PLANE : 0);
                #pragma unroll
                for (int kt = 0; kt < 4; kt++) {
                    uint32_t bfr[4][2];
                    #pragma unroll
                    for (int ng = 0; ng < 2; ng++) {
                        uint32_t bd = Bb + (kt * 16 + (lane & 15)) * ROWB
                                         + chB + ng * 32 + (lane >> 4) * 16;
                        uint32_t r0, r1, r2, r3;
                        LDSM4T(r0, r1, r2, r3, bd);
                        bfr[2 * ng][0] = r0; bfr[2 * ng][1] = r1;
                        bfr[2 * ng + 1][0] = r2; bfr[2 * ng + 1][1] = r3;
                    }
                    const uint32_t* af = (p == 2) ? pal[kt] : pah[kt];
                    #pragma unroll
                    for (int nt = 0; nt < 4; nt++)
                        MMA(o[nt], af, bfr[nt]);
                }
            }
            // store O (hi/lo) into x region
            #pragma unroll
            for (int nt = 0; nt < 4; nt++) {
                int ch = head * 32 + nt * 8 + 2 * t4;
                int tok = mbase + g;
                uint32_t hi, lo;
                split2(o[nt][0], o[nt][1], hi, lo);
                *(uint32_t*)(smem + XHI + tok * ROWB + ch * 2) = hi;
                *(uint32_t*)(smem + XLO + tok * ROWB + ch * 2) = lo;
                split2(o[nt][2], o[nt][3], hi, lo);
                *(uint32_t*)(smem + XHI + (tok + 8) * ROWB + ch * 2) = hi;
                *(uint32_t*)(smem + XLO + (tok + 8) * ROWB + ch * 2) = lo;
            }
        }
    }
    __syncthreads();   // O complete, Y reads done

    // ---- phase 3: proj = O @ Wproj + bias ----
    {
        const uint4* src = (const uint4*)(&g_wp[0][0]);
        uint4* dst = (uint4*)(smem + WBASE);
        for (int i = tid; i < (2 * WPLANE) / 16; i += 256) dst[i] = src[i];
    }
    __syncthreads();
    {
        const int mbase = (warp >> 2) * 32;
        const int nbase = (warp & 3) * 32;
        float acc[2][4][4];
        #pragma unroll
        for (int mt = 0; mt < 2; mt++)
            #pragma unroll
            for (int nt = 0; nt < 4; nt++)
                #pragma unroll
                for (int q = 0; q < 4; q++) acc[mt][nt][q] = 0.f;

        #pragma unroll
        for (int p = 0; p < 3; p++) {
            const uint32_t Ab = sb + ((p == 2) ? XLO : XHI);
            const uint32_t Bb = sb + WBASE + ((p == 1) ? WPLANE : 0);
            #pragma unroll
            for (int kt = 0; kt < 8; kt++) {
                uint32_t a[2][4], bfr[4][2];
                #pragma unroll
                for (int mt = 0; mt < 2; mt++) {
                    uint32_t ad = Ab + (mbase + mt * 16 + (lane & 15)) * ROWB
                                     + kt * 32 + (lane >> 4) * 16;
                    LDSM4(a[mt][0], a[mt][1], a[mt][2], a[mt][3], ad);
                }
                #pragma unroll
                for (int ng = 0; ng < 2; ng++) {
                    uint32_t bd = Bb + (nbase + ng * 16 + ((lane >> 4) << 3) + (lane & 7)) * ROWB
                                     + kt * 32 + ((lane >> 3) & 1) * 16;
                    uint32_t r0, r1, r2, r3;
                    LDSM4(r0, r1, r2, r3, bd);
                    bfr[2 * ng][0] = r0; bfr[2 * ng][1] = r1;
                    bfr[2 * ng + 1][0] = r2; bfr[2 * ng + 1][1] = r3;
                }
                #pragma unroll
                for (int mt = 0; mt < 2; mt++)
                    #pragma unroll
                    for (int nt = 0; nt < 4; nt++)
                        MMA(acc[mt][nt], a[mt], bfr[nt]);
            }
        }
        // epilogue: bias + swizzled f32 staging for coalesced scatter
        float* fin = (float*)(smem + FINO);
        const float* bias = (const float*)(smem + BIASO);
        #pragma unroll
        for (int mt = 0; mt < 2; mt++)
            #pragma unroll
            for (int nt = 0; nt < 4; nt++) {
                int c0 = nbase + nt * 8 + 2 * t4, c1 = c0 + 1;
                int tok = mbase + mt * 16 + g;
                fin[c0 * 64 + (tok ^ (c0 & 31))] = acc[mt][nt][0] + bias[c0];
                fin[c1 * 64 + (tok ^ (c1 & 31))] = acc[mt][nt][1] + bias[c1];
                fin[c0 * 64 + ((tok + 8) ^ (c0 & 31))] = acc[mt][nt][2] + bias[c0];
                fin[c1 * 64 + ((tok + 8) ^ (c1 & 31))] = acc[mt][nt][3] + bias[c1];
            }
    }
    __syncthreads();

    // ---- phase 4: coalesced scatter with reverse roll ----
    {
        const float* fin = (const float*)(smem + FINO);
        for (int i = tid; i < 64 * 128; i += 256) {
            int c = i >> 6, t = i & 63;
            int h = (hbase + (t >> 3)) & 255;
            int w = (wbase + (t & 7)) & 255;
            out[(((b * 128 + c) * 256) + h) * 256 + w] = fin[c * 64 + (t ^ (c & 31))];
        }
    }
}

extern "C" void kernel_launch(void* const* d_in, const int* in_sizes, int n_in,
                              void* d_out, int out_size)
{
    const float* x      = (const float*)d_in[0];
    const float* w_qkv  = (const float*)d_in[1];
    const float* w_proj = (const float*)d_in[2];
    const float* b_proj = (const float*)d_in[3];
    float* out = (float*)d_out;

    prep_weights<<<(4 * 128 * KPAD + 255) / 256, 256>>>(w_qkv, w_proj);

    cudaFuncSetAttribute(swin_mma_kernel,
                         cudaFuncAttributeMaxDynamicSharedMemorySize, SMEM_BYTES);
    swin_mma_kernel<<<8192, 256, SMEM_BYTES>>>(x, b_proj, out);
}

// round 4
// speedup vs baseline: 2.1503x; 1.0357x over previous
#include <cuda_runtime.h>
#include <cuda_bf16.h>
#include <cstdint>

// SwinStyleAttention via mma.sync bf16 hi/lo 3-pass. 1 CTA = 1 window (M=64),
// 512 threads / 16 warps for latency hiding (R3 was 256 thr, latency-bound).

#define KPAD   136                    // padded row stride (bf16); 272B rows: ldmatrix conflict-free
#define ROWB   (KPAD * 2)             // 272 bytes
#define PLANE  (64 * ROWB)            // 17408 B  [64][136] bf16
#define WPLANE (128 * ROWB)           // 34816 B  [128][136] bf16
#define XHI    0
#define XLO    PLANE
#define YBASE  (2 * PLANE)            // q_hi,q_lo,k_hi,k_lo,v_hi,v_lo planes
#define WBASE  (YBASE + 6 * PLANE)    // 139264: W hi plane + lo plane
#define BIASO  (WBASE + 2 * WPLANE)   // 208896
#define FINO   YBASE                  // f32 [128][64] overlay (Y dead by then)
#define SMEM_BYTES (BIASO + 512)
#define SCALE_ 0.17677669529663687f

// Pre-transposed, hi/lo-split weights: g_wq[nc][part][n*KPAD+k] = split(wqkv[k*384+nc*128+n])
__device__ __nv_bfloat16 g_wq[3][2][128 * KPAD];
__device__ __nv_bfloat16 g_wp[2][128 * KPAD];

static __device__ __forceinline__ uint32_t smem_u32(const void* p) {
    uint32_t a;
    asm("{ .reg .u64 t; cvta.to.shared.u64 t, %1; cvt.u32.u64 %0, t; }" : "=r"(a) : "l"(p));
    return a;
}

#define LDSM4(R0, R1, R2, R3, ADDR) \
    asm volatile("ldmatrix.sync.aligned.m8n8.x4.shared.b16 {%0,%1,%2,%3}, [%4];" \
                 : "=r"(R0), "=r"(R1), "=r"(R2), "=r"(R3) : "r"(ADDR))
#define LDSM4T(R0, R1, R2, R3, ADDR) \
    asm volatile("ldmatrix.sync.aligned.m8n8.x4.trans.shared.b16 {%0,%1,%2,%3}, [%4];" \
                 : "=r"(R0), "=r"(R1), "=r"(R2), "=r"(R3) : "r"(ADDR))
#define MMA(D, A, B) \
    asm volatile("mma.sync.aligned.m16n8k16.row.col.f32.bf16.bf16.f32 " \
                 "{%0,%1,%2,%3},{%4,%5,%6,%7},{%8,%9},{%0,%1,%2,%3};" \
                 : "+f"((D)[0]), "+f"((D)[1]), "+f"((D)[2]), "+f"((D)[3]) \
                 : "r"((A)[0]), "r"((A)[1]), "r"((A)[2]), "r"((A)[3]), \
                   "r"((B)[0]), "r"((B)[1]))
#define CP_ASYNC16(DST, SRC) \
    asm volatile("cp.async.cg.shared.global [%0], [%1], 16;" :: "r"(DST), "l"(SRC))
#define CP_COMMIT_WAIT() do { \
    asm volatile("cp.async.commit_group;"); \
    asm volatile("cp.async.wait_group 0;"); } while (0)

static __device__ __forceinline__ void split2(float x, float y, uint32_t& hi, uint32_t& lo) {
    __nv_bfloat16 hx = __float2bfloat16(x), hy = __float2bfloat16(y);
    __nv_bfloat16 lx = __float2bfloat16(x - __bfloat162float(hx));
    __nv_bfloat16 ly = __float2bfloat16(y - __bfloat162float(hy));
    hi = (uint32_t)__bfloat16_as_ushort(hx) | ((uint32_t)__bfloat16_as_ushort(hy) << 16);
    lo = (uint32_t)__bfloat16_as_ushort(lx) | ((uint32_t)__bfloat16_as_ushort(ly) << 16);
}

// ---------------- prep: transpose + hi/lo split weights ----------------
__global__ void prep_weights(const float* __restrict__ wqkv, const float* __restrict__ wproj) {
    int i = blockIdx.x * blockDim.x + threadIdx.x;
    if (i < 3 * 128 * KPAD) {
        int k = i % KPAD, n = (i / KPAD) & 127, nc = i / (KPAD * 128);
        float v = (k < 128) ? wqkv[k * 384 + nc * 128 + n] : 0.f;
        __nv_bfloat16 h = __float2bfloat16(v);
        g_wq[nc][0][n * KPAD + k] = h;
        g_wq[nc][1][n * KPAD + k] = __float2bfloat16(v - __bfloat162float(h));
    } else if (i < 3 * 128 * KPAD + 128 * KPAD) {
        int j = i - 3 * 128 * KPAD;
        int k = j % KPAD, n = j / KPAD;
        float v = (k < 128) ? wproj[k * 128 + n] : 0.f;
        __nv_bfloat16 h = __float2bfloat16(v);
        g_wp[0][n * KPAD + k] = h;
        g_wp[1][n * KPAD + k] = __float2bfloat16(v - __bfloat162float(h));
    }
}

// ---------------- main fused kernel ----------------
__global__ __launch_bounds__(512, 1)
void swin_mma2_kernel(const float* __restrict__ x,
                      const float* __restrict__ b_proj,
                      float* __restrict__ out)
{
    extern __shared__ __align__(16) unsigned char smem[];
    const uint32_t sb = smem_u32(smem);

    const int tid = threadIdx.x;
    const int lane = tid & 31;
    const int warp = tid >> 5;     // 0..15
    const int g = lane >> 2;
    const int t4 = lane & 3;

    const int win = blockIdx.x;
    const int b = win >> 10, wy = (win >> 5) & 31, wx = win & 31;
    const int hbase = wy * 8 + 4, wbase = wx * 8 + 4;

    // ---- phase 0: bias + rolled-window gather, split into x hi/lo planes ----
    if (tid < 128) ((float*)(smem + BIASO))[tid] = b_proj[tid];
    for (int i = tid; i < 64 * 128; i += 512) {
        int c = i >> 6, t = i & 63;
        int h = (hbase + (t >> 3)) & 255;
        int w = (wbase + (t & 7)) & 255;
        float v = x[(((b * 128 + c) * 256) + h) * 256 + w];
        __nv_bfloat16 hv = __float2bfloat16(v);
        *(__nv_bfloat16*)(smem + XHI + t * ROWB + c * 2) = hv;
        *(__nv_bfloat16*)(smem + XLO + t * ROWB + c * 2) =
            __float2bfloat16(v - __bfloat162float(hv));
    }

    const int mbase = (warp >> 2) * 16;   // 4 M groups of 16 rows
    const int nbase = (warp & 3) * 32;    // 4 N groups of 32 cols

    // ---- phase 1: qkv = x @ Wqkv, 3 N-chunks of 128 (q, k, v) ----
    for (int nc = 0; nc < 3; nc++) {
        __syncthreads();                                    // W buffer free / x ready
        {
            const unsigned char* src = (const unsigned char*)(&g_wq[nc][0][0]);
            for (int i = tid; i < (2 * WPLANE) / 16; i += 512)
                CP_ASYNC16(sb + WBASE + i * 16, src + i * 16);
            CP_COMMIT_WAIT();
        }
        __syncthreads();                                    // W ready

        float acc[4][4];
        #pragma unroll
        for (int nt = 0; nt < 4; nt++)
            #pragma unroll
            for (int q = 0; q < 4; q++) acc[nt][q] = 0.f;

        #pragma unroll
        for (int p = 0; p < 3; p++) {                       // (h,h),(h,l),(l,h)
            const uint32_t Ab = sb + ((p == 2) ? XLO : XHI);
            const uint32_t Bb = sb + WBASE + ((p == 1) ? WPLANE : 0);
            #pragma unroll
            for (int kt = 0; kt < 8; kt++) {
                uint32_t a[4], bfr[4][2];
                uint32_t ad = Ab + (mbase + (lane & 15)) * ROWB
                                 + kt * 32 + (lane >> 4) * 16;
                LDSM4(a[0], a[1], a[2], a[3], ad);
                #pragma unroll
                for (int ng = 0; ng < 2; ng++) {
                    uint32_t bd = Bb + (nbase + ng * 16 + ((lane >> 4) << 3) + (lane & 7)) * ROWB
                                     + kt * 32 + ((lane >> 3) & 1) * 16;
                    uint32_t r0, r1, r2, r3;
                    LDSM4(r0, r1, r2, r3, bd);
                    bfr[2 * ng][0] = r0; bfr[2 * ng][1] = r1;
                    bfr[2 * ng + 1][0] = r2; bfr[2 * ng + 1][1] = r3;
                }
                #pragma unroll
                for (int nt = 0; nt < 4; nt++)
                    MMA(acc[nt], a, bfr[nt]);
            }
        }
        // epilogue: split to Y hi/lo planes (chunk nc)
        unsigned char* Yh = smem + YBASE + nc * 2 * PLANE;
        unsigned char* Yl = Yh + PLANE;
        #pragma unroll
        for (int nt = 0; nt < 4; nt++) {
            int ch = nbase + nt * 8 + 2 * t4;
            int tok = mbase + g;
            uint32_t hi, lo;
            split2(acc[nt][0], acc[nt][1], hi, lo);
            *(uint32_t*)(Yh + tok * ROWB + ch * 2) = hi;
            *(uint32_t*)(Yl + tok * ROWB + ch * 2) = lo;
            split2(acc[nt][2], acc[nt][3], hi, lo);
            *(uint32_t*)(Yh + (tok + 8) * ROWB + ch * 2) = hi;
            *(uint32_t*)(Yl + (tok + 8) * ROWB + ch * 2) = lo;
        }
    }
    __syncthreads();   // Y complete; x planes now dead -> reuse as O planes

    // ---- phase 2: attention. warp -> (head, 16-row quarter) ----
    {
        const int head = warp >> 2;
        const int mq = warp & 3;
        const int ambase = mq * 16;
        const uint32_t Yq = sb + YBASE, Yk = Yq + 2 * PLANE, Yv = Yk + 2 * PLANE;
        const int chB = head * 64;                 // byte offset of head slice

        float s[8][4];
        #pragma unroll
        for (int nt = 0; nt < 8; nt++)
            #pragma unroll
            for (int q = 0; q < 4; q++) s[nt][q] = 0.f;

        // QK^T
        #pragma unroll
        for (int p = 0; p < 3; p++) {
            const uint32_t Ab = Yq + ((p == 2) ? PLANE : 0);
            const uint32_t Bb = Yk + ((p == 1) ? PLANE : 0);
            #pragma unroll
            for (int kt = 0; kt < 2; kt++) {
                uint32_t a[4];
                uint32_t ad = Ab + (ambase + (lane & 15)) * ROWB
                                 + chB + kt * 32 + (lane >> 4) * 16;
                LDSM4(a[0], a[1], a[2], a[3], ad);
                #pragma unroll
                for (int ng = 0; ng < 4; ng++) {
                    uint32_t bd = Bb + (ng * 16 + ((lane >> 4) << 3) + (lane & 7)) * ROWB
                                     + chB + kt * 32 + ((lane >> 3) & 1) * 16;
                    uint32_t r0, r1, r2, r3;
                    LDSM4(r0, r1, r2, r3, bd);
                    uint32_t b0[2] = {r0, r1}, b1[2] = {r2, r3};
                    MMA(s[2 * ng], a, b0);
                    MMA(s[2 * ng + 1], a, b1);
                }
            }
        }
        // softmax (rows g and g+8; quad lanes share a row)
        float mx0 = -1e30f, mx1 = -1e30f;
        #pragma unroll
        for (int nt = 0; nt < 8; nt++) {
            #pragma unroll
            for (int q = 0; q < 4; q++) s[nt][q] *= SCALE_;
            mx0 = fmaxf(mx0, fmaxf(s[nt][0], s[nt][1]));
            mx1 = fmaxf(mx1, fmaxf(s[nt][2], s[nt][3]));
        }
        mx0 = fmaxf(mx0, __shfl_xor_sync(0xffffffffu, mx0, 1));
        mx0 = fmaxf(mx0, __shfl_xor_sync(0xffffffffu, mx0, 2));
        mx1 = fmaxf(mx1, __shfl_xor_sync(0xffffffffu, mx1, 1));
        mx1 = fmaxf(mx1, __shfl_xor_sync(0xffffffffu, mx1, 2));
        float sm0 = 0.f, sm1 = 0.f;
        #pragma unroll
        for (int nt = 0; nt < 8; nt++) {
            s[nt][0] = __expf(s[nt][0] - mx0); sm0 += s[nt][0];
            s[nt][1] = __expf(s[nt][1] - mx0); sm0 += s[nt][1];
            s[nt][2] = __expf(s[nt][2] - mx1); sm1 += s[nt][2];
            s[nt][3] = __expf(s[nt][3] - mx1); sm1 += s[nt][3];
        }
        sm0 += __shfl_xor_sync(0xffffffffu, sm0, 1);
        sm0 += __shfl_xor_sync(0xffffffffu, sm0, 2);
        sm1 += __shfl_xor_sync(0xffffffffu, sm1, 1);
        sm1 += __shfl_xor_sync(0xffffffffu, sm1, 2);
        const float inv0 = 1.f / sm0, inv1 = 1.f / sm1;

        // P -> A fragments (hi/lo), directly from score regs
        uint32_t pah[4][4], pal[4][4];
        #pragma unroll
        for (int kk = 0; kk < 4; kk++) {
            split2(s[2 * kk][0] * inv0, s[2 * kk][1] * inv0, pah[kk][0], pal[kk][0]);
            split2(s[2 * kk][2] * inv1, s[2 * kk][3] * inv1, pah[kk][1], pal[kk][1]);
            split2(s[2 * kk + 1][0] * inv0, s[2 * kk + 1][1] * inv0, pah[kk][2], pal[kk][2]);
            split2(s[2 * kk + 1][2] * inv1, s[2 * kk + 1][3] * inv1, pah[kk][3], pal[kk][3]);
        }

        // P @ V
        float o[4][4];
        #pragma unroll
        for (int nt = 0; nt < 4; nt++)
            #pragma unroll
            for (int q = 0; q < 4; q++) o[nt][q] = 0.f;
        #pragma unroll
        for (int p = 0; p < 3; p++) {
            const uint32_t Bb = Yv + ((p == 1) ? PLANE : 0);
            #pragma unroll
            for (int kt = 0; kt < 4; kt++) {
                uint32_t bfr[4][2];
                #pragma unroll
                for (int ng = 0; ng < 2; ng++) {
                    uint32_t bd = Bb + (kt * 16 + (lane & 15)) * ROWB
                                     + chB + ng * 32 + (lane >> 4) * 16;
                    uint32_t r0, r1, r2, r3;
                    LDSM4T(r0, r1, r2, r3, bd);
                    bfr[2 * ng][0] = r0; bfr[2 * ng][1] = r1;
                    bfr[2 * ng + 1][0] = r2; bfr[2 * ng + 1][1] = r3;
                }
                const uint32_t* af = (p == 2) ? pal[kt] : pah[kt];
                #pragma unroll
                for (int nt = 0; nt < 4; nt++)
                    MMA(o[nt], af, bfr[nt]);
            }
        }
        // store O (hi/lo) into x region
        #pragma unroll
        for (int nt = 0; nt < 4; nt++) {
            int ch = head * 32 + nt * 8 + 2 * t4;
            int tok = ambase + g;
            uint32_t hi, lo;
            split2(o[nt][0], o[nt][1], hi, lo);
            *(uint32_t*)(smem + XHI + tok * ROWB + ch * 2) = hi;
            *(uint32_t*)(smem + XLO + tok * ROWB + ch * 2) = lo;
            split2(o[nt][2], o[nt][3], hi, lo);
            *(uint32_t*)(smem + XHI + (tok + 8) * ROWB + ch * 2) = hi;
            *(uint32_t*)(smem + XLO + (tok + 8) * ROWB + ch * 2) = lo;
        }
    }
    __syncthreads();   // O complete, Y reads done

    // ---- phase 3: proj = O @ Wproj + bias ----
    {
        const unsigned char* src = (const unsigned char*)(&g_wp[0][0]);
        for (int i = tid; i < (2 * WPLANE) / 16; i += 512)
            CP_ASYNC16(sb + WBASE + i * 16, src + i * 16);
        CP_COMMIT_WAIT();
    }
    __syncthreads();
    {
        float acc[4][4];
        #pragma unroll
        for (int nt = 0; nt < 4; nt++)
            #pragma unroll
            for (int q = 0; q < 4; q++) acc[nt][q] = 0.f;

        #pragma unroll
        for (int p = 0; p < 3; p++) {
            const uint32_t Ab = sb + ((p == 2) ? XLO : XHI);
            const uint32_t Bb = sb + WBASE + ((p == 1) ? WPLANE : 0);
            #pragma unroll
            for (int kt = 0; kt < 8; kt++) {
                uint32_t a[4], bfr[4][2];
                uint32_t ad = Ab + (mbase + (lane & 15)) * ROWB
                                 + kt * 32 + (lane >> 4) * 16;
                LDSM4(a[0], a[1], a[2], a[3], ad);
                #pragma unroll
                for (int ng = 0; ng < 2; ng++) {
                    uint32_t bd = Bb + (nbase + ng * 16 + ((lane >> 4) << 3) + (lane & 7)) * ROWB
                                     + kt * 32 + ((lane >> 3) & 1) * 16;
                    uint32_t r0, r1, r2, r3;
                    LDSM4(r0, r1, r2, r3, bd);
                    bfr[2 * ng][0] = r0; bfr[2 * ng][1] = r1;
                    bfr[2 * ng + 1][0] = r2; bfr[2 * ng + 1][1] = r3;
                }
                #pragma unroll
                for (int nt = 0; nt < 4; nt++)
                    MMA(acc[nt], a, bfr[nt]);
            }
        }
        // epilogue: bias + swizzled f32 staging for coalesced scatter
        float* fin = (float*)(smem + FINO);
        const float* bias = (const float*)(smem + BIASO);
        #pragma unroll
        for (int nt = 0; nt < 4; nt++) {
            int c0 = nbase + nt * 8 + 2 * t4, c1 = c0 + 1;
            int tok = mbase + g;
            fin[c0 * 64 + (tok ^ (c0 & 31))] = acc[nt][0] + bias[c0];
            fin[c1 * 64 + (tok ^ (c1 & 31))] = acc[nt][1] + bias[c1];
            fin[c0 * 64 + ((tok + 8) ^ (c0 & 31))] = acc[nt][2] + bias[c0];
            fin[c1 * 64 + ((tok + 8) ^ (c1 & 31))] = acc[nt][3] + bias[c1];
        }
    }
    __syncthreads();

    // ---- phase 4: coalesced scatter with reverse roll ----
    {
        const float* fin = (const float*)(smem + FINO);
        for (int i = tid; i < 64 * 128; i += 512) {
            int c = i >> 6, t = i & 63;
            int h = (hbase + (t >> 3)) & 255;
            int w = (wbase + (t & 7)) & 255;
            out[(((b * 128 + c) * 256) + h) * 256 + w] = fin[c * 64 + (t ^ (c & 31))];
        }
    }
}

extern "C" void kernel_launch(void* const* d_in, const int* in_sizes, int n_in,
                              void* d_out, int out_size)
{
    const float* x      = (const float*)d_in[0];
    const float* w_qkv  = (const float*)d_in[1];
    const float* w_proj = (const float*)d_in[2];
    const float* b_proj = (const float*)d_in[3];
    float* out = (float*)d_out;

    prep_weights<<<(4 * 128 * KPAD + 255) / 256, 256>>>(w_qkv, w_proj);

    cudaFuncSetAttribute(swin_mma2_kernel,
                         cudaFuncAttributeMaxDynamicSharedMemorySize, SMEM_BYTES);
    swin_mma2_kernel<<<8192, 512, SMEM_BYTES>>>(x, b_proj, out);
}

// round 5
// speedup vs baseline: 2.3525x; 1.0940x over previous
#include <cuda_runtime.h>
#include <cuda_bf16.h>
#include <cstdint>

// SwinStyleAttention, mma.sync bf16 hi/lo 3-pass, smem-traffic-optimized:
// fragment reuse (6 ldsm/kt instead of 9), XOR-swizzled 256B rows (no pad),
// 3-plane W rotation with cp.async prefetch. 1 CTA = 1 window, 512 threads.

#define SCALE_ 0.17677669529663687f
// swizzled byte address within a plane: 128 rows x 256B
#define SWZ(row, colb) (((row) << 8) + ((colb) ^ (((row) & 7) << 4)))

// plane byte offsets
#define XHI   0
#define XLO   16384
#define YQH   32768
#define YQL   49152
#define YKH   65536
#define YKL   81920
#define YVH   98304
#define YVL   114688
#define PW(i) (131072 + (i) * 32768)
#define BIASO 229376
#define FINO  32768              // f32 [128][64] overlay on YQ planes (dead by proj epilogue)
#define SMEM_BYTES 229888

// swizzled weight plane images: [n*128 + (k ^ ((n&7)<<3))], 16384 bf16 = 32KB each
__device__ __nv_bfloat16 g_wq[3][2][16384];
__device__ __nv_bfloat16 g_wp[2][16384];

static __device__ __forceinline__ uint32_t smem_u32(const void* p) {
    uint32_t a;
    asm("{ .reg .u64 t; cvta.to.shared.u64 t, %1; cvt.u32.u64 %0, t; }" : "=r"(a) : "l"(p));
    return a;
}

#define LDSM4(R0, R1, R2, R3, ADDR) \
    asm volatile("ldmatrix.sync.aligned.m8n8.x4.shared.b16 {%0,%1,%2,%3}, [%4];" \
                 : "=r"(R0), "=r"(R1), "=r"(R2), "=r"(R3) : "r"(ADDR))
#define LDSM4T(R0, R1, R2, R3, ADDR) \
    asm volatile("ldmatrix.sync.aligned.m8n8.x4.trans.shared.b16 {%0,%1,%2,%3}, [%4];" \
                 : "=r"(R0), "=r"(R1), "=r"(R2), "=r"(R3) : "r"(ADDR))
#define MMA(D, A, B) \
    asm volatile("mma.sync.aligned.m16n8k16.row.col.f32.bf16.bf16.f32 " \
                 "{%0,%1,%2,%3},{%4,%5,%6,%7},{%8,%9},{%0,%1,%2,%3};" \
                 : "+f"((D)[0]), "+f"((D)[1]), "+f"((D)[2]), "+f"((D)[3]) \
                 : "r"((A)[0]), "r"((A)[1]), "r"((A)[2]), "r"((A)[3]), \
                   "r"((B)[0]), "r"((B)[1]))
#define CP_ASYNC16(DST, SRC) \
    asm volatile("cp.async.cg.shared.global [%0], [%1], 16;" :: "r"(DST), "l"(SRC))
#define CP_COMMIT() asm volatile("cp.async.commit_group;")
#define CP_WAIT0()  asm volatile("cp.async.wait_group 0;")

static __device__ __forceinline__ void split2(float x, float y, uint32_t& hi, uint32_t& lo) {
    __nv_bfloat16 hx = __float2bfloat16(x), hy = __float2bfloat16(y);
    __nv_bfloat16 lx = __float2bfloat16(x - __bfloat162float(hx));
    __nv_bfloat16 ly = __float2bfloat16(y - __bfloat162float(hy));
    hi = (uint32_t)__bfloat16_as_ushort(hx) | ((uint32_t)__bfloat16_as_ushort(hy) << 16);
    lo = (uint32_t)__bfloat16_as_ushort(lx) | ((uint32_t)__bfloat16_as_ushort(ly) << 16);
}

// ---------------- prep: transpose + hi/lo split weights into swizzled planes --------------
__global__ void prep_weights(const float* __restrict__ wqkv, const float* __restrict__ wproj) {
    int i = blockIdx.x * blockDim.x + threadIdx.x;
    if (i < 49152) {                                   // 3 chunks x 128 n x 128 k
        int k = i & 127, n = (i >> 7) & 127, nc = i >> 14;
        float v = wqkv[k * 384 + nc * 128 + n];
        __nv_bfloat16 h = __float2bfloat16(v);
        int off = n * 128 + (k ^ ((n & 7) << 3));
        g_wq[nc][0][off] = h;
        g_wq[nc][1][off] = __float2bfloat16(v - __bfloat162float(h));
    } else if (i < 65536) {
        int j = i - 49152;
        int k = j & 127, n = (j >> 7) & 127;
        float v = wproj[k * 128 + n];
        __nv_bfloat16 h = __float2bfloat16(v);
        int off = n * 128 + (k ^ ((n & 7) << 3));
        g_wp[0][off] = h;
        g_wp[1][off] = __float2bfloat16(v - __bfloat162float(h));
    }
}

// ---------------- main fused kernel ----------------
__global__ __launch_bounds__(512, 1)
void swin_mma3_kernel(const float* __restrict__ x,
                      const float* __restrict__ b_proj,
                      float* __restrict__ out)
{
    extern __shared__ __align__(256) unsigned char smem[];
    const uint32_t sb = smem_u32(smem);

    const int tid = threadIdx.x;
    const int lane = tid & 31;
    const int warp = tid >> 5;     // 0..15
    const int g = lane >> 2;
    const int t4 = lane & 3;

    const int win = blockIdx.x;
    const int b = win >> 10, wy = (win >> 5) & 31, wx = win & 31;
    const int hbase = wy * 8 + 4, wbase = wx * 8 + 4;

    // cp.async one 32KB plane (all 512 threads participate); caller commits via lambda
    auto cpplane = [&](uint32_t dstPlane, const __nv_bfloat16* src) {
        const char* s = (const char*)src;
        #pragma unroll
        for (int i = 0; i < 4; i++) {
            int off = (tid + i * 512) * 16;
            CP_ASYNC16(sb + dstPlane + off, s + off);
        }
        CP_COMMIT();
    };

    // prefetch W: q hi/lo + k hi
    cpplane(PW(0), g_wq[0][0]);
    cpplane(PW(1), g_wq[0][1]);
    cpplane(PW(2), g_wq[1][0]);

    // ---- phase 0: bias + rolled-window gather, split into x hi/lo planes ----
    if (tid < 128) ((float*)(smem + BIASO))[tid] = b_proj[tid];
    for (int i = tid; i < 64 * 128; i += 512) {
        int c = i >> 6, t = i & 63;
        int h = (hbase + (t >> 3)) & 255;
        int w = (wbase + (t & 7)) & 255;
        float v = x[(((b * 128 + c) * 256) + h) * 256 + w];
        __nv_bfloat16 hv = __float2bfloat16(v);
        *(__nv_bfloat16*)(smem + XHI + SWZ(t, c * 2)) = hv;
        *(__nv_bfloat16*)(smem + XLO + SWZ(t, c * 2)) =
            __float2bfloat16(v - __bfloat162float(hv));
    }
    CP_WAIT0();
    __syncthreads();

    const int mbase = (warp >> 2) * 16;   // 4 M groups of 16 rows
    const int nbase = (warp & 3) * 32;    // 4 N groups of 32 cols

    // GEMM chunk: C[64x128] = X(hi/lo) @ W(hi/lo), 3-product compensation,
    // fragment-reuse ordering: 6 ldsm -> 12 MMA per kt.
    auto gemm_chunk = [&](uint32_t whi, uint32_t wlo, uint32_t yh, uint32_t yl) {
        float acc[4][4];
        #pragma unroll
        for (int nt = 0; nt < 4; nt++)
            #pragma unroll
            for (int q = 0; q < 4; q++) acc[nt][q] = 0.f;

        const int arow = mbase + (lane & 15);
        const int brow = nbase + ((lane >> 4) << 3) + (lane & 7);
        #pragma unroll
        for (int kt = 0; kt < 8; kt++) {
            const int acolb = kt * 32 + (lane >> 4) * 16;
            const int bcolb = kt * 32 + ((lane >> 3) & 1) * 16;
            uint32_t ah[4], al[4], bh[4][2], bl[4][2];
            LDSM4(ah[0], ah[1], ah[2], ah[3], sb + XHI + SWZ(arow, acolb));
            LDSM4(al[0], al[1], al[2], al[3], sb + XLO + SWZ(arow, acolb));
            #pragma unroll
            for (int ng = 0; ng < 2; ng++) {
                uint32_t r0, r1, r2, r3;
                LDSM4(r0, r1, r2, r3, sb + whi + SWZ(brow + ng * 16, bcolb));
                bh[2 * ng][0] = r0; bh[2 * ng][1] = r1;
                bh[2 * ng + 1][0] = r2; bh[2 * ng + 1][1] = r3;
                LDSM4(r0, r1, r2, r3, sb + wlo + SWZ(brow + ng * 16, bcolb));
                bl[2 * ng][0] = r0; bl[2 * ng][1] = r1;
                bl[2 * ng + 1][0] = r2; bl[2 * ng + 1][1] = r3;
            }
            #pragma unroll
            for (int nt = 0; nt < 4; nt++) {
                MMA(acc[nt], ah, bh[nt]);
                MMA(acc[nt], ah, bl[nt]);
                MMA(acc[nt], al, bh[nt]);
            }
        }
        // epilogue: split to Y hi/lo planes
        #pragma unroll
        for (int nt = 0; nt < 4; nt++) {
            int ch = nbase + nt * 8 + 2 * t4;
            int tok = mbase + g;
            uint32_t hi, lo;
            split2(acc[nt][0], acc[nt][1], hi, lo);
            *(uint32_t*)(smem + yh + SWZ(tok, ch * 2)) = hi;
            *(uint32_t*)(smem + yl + SWZ(tok, ch * 2)) = lo;
            split2(acc[nt][2], acc[nt][3], hi, lo);
            *(uint32_t*)(smem + yh + SWZ(tok + 8, ch * 2)) = hi;
            *(uint32_t*)(smem + yl + SWZ(tok + 8, ch * 2)) = lo;
        }
    };

    // ---- phase 1: qkv, 3 chunks with W-plane rotation ----
    gemm_chunk(PW(0), PW(1), YQH, YQL);            // q: hi=P0, lo=P1
    __syncthreads();
    cpplane(PW(0), g_wq[1][1]);                    // lo(k) -> P0
    cpplane(PW(1), g_wq[2][0]);                    // hi(v) -> P1
    CP_WAIT0();
    __syncthreads();
    gemm_chunk(PW(2), PW(0), YKH, YKL);            // k: hi=P2, lo=P0
    __syncthreads();
    cpplane(PW(2), g_wq[2][1]);                    // lo(v) -> P2
    CP_WAIT0();
    __syncthreads();
    gemm_chunk(PW(1), PW(2), YVH, YVL);            // v: hi=P1, lo=P2
    __syncthreads();

    // prefetch proj weights under the attention phase
    cpplane(PW(0), g_wp[0]);
    cpplane(PW(1), g_wp[1]);

    // ---- phase 2: attention. warp -> (head, 16-row quarter) ----
    {
        const int head = warp >> 2;
        const int ambase = (warp & 3) * 16;
        const int chB = head * 64;                 // byte offset of head's 32 channels

        float s[8][4];
        #pragma unroll
        for (int nt = 0; nt < 8; nt++)
            #pragma unroll
            for (int q = 0; q < 4; q++) s[nt][q] = 0.f;

        // QK^T with fragment reuse: per kt: Qh,Ql once; per ng: Kh,Kl once -> 3 products
        #pragma unroll
        for (int kt = 0; kt < 2; kt++) {
            const int acolb = chB + kt * 32 + (lane >> 4) * 16;
            const int bcolb = chB + kt * 32 + ((lane >> 3) & 1) * 16;
            uint32_t qh[4], ql[4];
            LDSM4(qh[0], qh[1], qh[2], qh[3], sb + YQH + SWZ(ambase + (lane & 15), acolb));
            LDSM4(ql[0], ql[1], ql[2], ql[3], sb + YQL + SWZ(ambase + (lane & 15), acolb));
            #pragma unroll
            for (int ng = 0; ng < 4; ng++) {
                const int brow = ng * 16 + ((lane >> 4) << 3) + (lane & 7);
                uint32_t h0, h1, h2, h3, l0, l1, l2, l3;
                LDSM4(h0, h1, h2, h3, sb + YKH + SWZ(brow, bcolb));
                LDSM4(l0, l1, l2, l3, sb + YKL + SWZ(brow, bcolb));
                uint32_t fh0[2] = {h0, h1}, fh1[2] = {h2, h3};
                uint32_t fl0[2] = {l0, l1}, fl1[2] = {l2, l3};
                MMA(s[2 * ng], qh, fh0);     MMA(s[2 * ng + 1], qh, fh1);
                MMA(s[2 * ng], qh, fl0);     MMA(s[2 * ng + 1], qh, fl1);
                MMA(s[2 * ng], ql, fh0);     MMA(s[2 * ng + 1], ql, fh1);
            }
        }
        // softmax (rows g and g+8; quad lanes share a row)
        float mx0 = -1e30f, mx1 = -1e30f;
        #pragma unroll
        for (int nt = 0; nt < 8; nt++) {
            #pragma unroll
            for (int q = 0; q < 4; q++) s[nt][q] *= SCALE_;
            mx0 = fmaxf(mx0, fmaxf(s[nt][0], s[nt][1]));
            mx1 = fmaxf(mx1, fmaxf(s[nt][2], s[nt][3]));
        }
        mx0 = fmaxf(mx0, __shfl_xor_sync(0xffffffffu, mx0, 1));
        mx0 = fmaxf(mx0, __shfl_xor_sync(0xffffffffu, mx0, 2));
        mx1 = fmaxf(mx1, __shfl_xor_sync(0xffffffffu, mx1, 1));
        mx1 = fmaxf(mx1, __shfl_xor_sync(0xffffffffu, mx1, 2));
        float sm0 = 0.f, sm1 = 0.f;
        #pragma unroll
        for (int nt = 0; nt < 8; nt++) {
            s[nt][0] = __expf(s[nt][0] - mx0); sm0 += s[nt][0];
            s[nt][1] = __expf(s[nt][1] - mx0); sm0 += s[nt][1];
            s[nt][2] = __expf(s[nt][2] - mx1); sm1 += s[nt][2];
            s[nt][3] = __expf(s[nt][3] - mx1); sm1 += s[nt][3];
        }
        sm0 += __shfl_xor_sync(0xffffffffu, sm0, 1);
        sm0 += __shfl_xor_sync(0xffffffffu, sm0, 2);
        sm1 += __shfl_xor_sync(0xffffffffu, sm1, 1);
        sm1 += __shfl_xor_sync(0xffffffffu, sm1, 2);
        const float inv0 = 1.f / sm0, inv1 = 1.f / sm1;

        // P -> A fragments (hi/lo)
        uint32_t pah[4][4], pal[4][4];
        #pragma unroll
        for (int kk = 0; kk < 4; kk++) {
            split2(s[2 * kk][0] * inv0, s[2 * kk][1] * inv0, pah[kk][0], pal[kk][0]);
            split2(s[2 * kk][2] * inv1, s[2 * kk][3] * inv1, pah[kk][1], pal[kk][1]);
            split2(s[2 * kk + 1][0] * inv0, s[2 * kk + 1][1] * inv0, pah[kk][2], pal[kk][2]);
            split2(s[2 * kk + 1][2] * inv1, s[2 * kk + 1][3] * inv1, pah[kk][3], pal[kk][3]);
        }

        // P @ V with V hi/lo loaded once per (kt, ng)
        float o[4][4];
        #pragma unroll
        for (int nt = 0; nt < 4; nt++)
            #pragma unroll
            for (int q = 0; q < 4; q++) o[nt][q] = 0.f;
        #pragma unroll
        for (int kt = 0; kt < 4; kt++) {
            const int vrow = kt * 16 + (lane & 15);
            uint32_t vh[4][2], vl[4][2];
            #pragma unroll
            for (int ng = 0; ng < 2; ng++) {
                const int vcolb = chB + ng * 32 + (lane >> 4) * 16;
                uint32_t r0, r1, r2, r3;
                LDSM4T(r0, r1, r2, r3, sb + YVH + SWZ(vrow, vcolb));
                vh[2 * ng][0] = r0; vh[2 * ng][1] = r1;
                vh[2 * ng + 1][0] = r2; vh[2 * ng + 1][1] = r3;
                LDSM4T(r0, r1, r2, r3, sb + YVL + SWZ(vrow, vcolb));
                vl[2 * ng][0] = r0; vl[2 * ng][1] = r1;
                vl[2 * ng + 1][0] = r2; vl[2 * ng + 1][1] = r3;
            }
            #pragma unroll
            for (int nt = 0; nt < 4; nt++) {
                MMA(o[nt], pah[kt], vh[nt]);
                MMA(o[nt], pah[kt], vl[nt]);
                MMA(o[nt], pal[kt], vh[nt]);
            }
        }
        // store O (hi/lo) into x planes
        #pragma unroll
        for (int nt = 0; nt < 4; nt++) {
            int ch = head * 32 + nt * 8 + 2 * t4;
            int tok = ambase + g;
            uint32_t hi, lo;
            split2(o[nt][0], o[nt][1], hi, lo);
            *(uint32_t*)(smem + XHI + SWZ(tok, ch * 2)) = hi;
            *(uint32_t*)(smem + XLO + SWZ(tok, ch * 2)) = lo;
            split2(o[nt][2], o[nt][3], hi, lo);
            *(uint32_t*)(smem + XHI + SWZ(tok + 8, ch * 2)) = hi;
            *(uint32_t*)(smem + XLO + SWZ(tok + 8, ch * 2)) = lo;
        }
    }
    CP_WAIT0();        // proj weights arrived (issued before attention)
    __syncthreads();   // O complete, Y reads done

    // ---- phase 3: proj = O @ Wproj + bias ----
    {
        float acc[4][4];
        #pragma unroll
        for (int nt = 0; nt < 4; nt++)
            #pragma unroll
            for (int q = 0; q < 4; q++) acc[nt][q] = 0.f;

        const int arow = mbase + (lane & 15);
        const int brow = nbase + ((lane >> 4) << 3) + (lane & 7);
        #pragma unroll
        for (int kt = 0; kt < 8; kt++) {
            const int acolb = kt * 32 + (lane >> 4) * 16;
            const int bcolb = kt * 32 + ((lane >> 3) & 1) * 16;
            uint32_t ah[4], al[4], bh[4][2], bl[4][2];
            LDSM4(ah[0], ah[1], ah[2], ah[3], sb + XHI + SWZ(arow, acolb));
            LDSM4(al[0], al[1], al[2], al[3], sb + XLO + SWZ(arow, acolb));
            #pragma unroll
            for (int ng = 0; ng < 2; ng++) {
                uint32_t r0, r1, r2, r3;
                LDSM4(r0, r1, r2, r3, sb + PW(0) + SWZ(brow + ng * 16, bcolb));
                bh[2 * ng][0] = r0; bh[2 * ng][1] = r1;
                bh[2 * ng + 1][0] = r2; bh[2 * ng + 1][1] = r3;
                LDSM4(r0, r1, r2, r3, sb + PW(1) + SWZ(brow + ng * 16, bcolb));
                bl[2 * ng][0] = r0; bl[2 * ng][1] = r1;
                bl[2 * ng + 1][0] = r2; bl[2 * ng + 1][1] = r3;
            }
            #pragma unroll
            for (int nt = 0; nt < 4; nt++) {
                MMA(acc[nt], ah, bh[nt]);
                MMA(acc[nt], ah, bl[nt]);
                MMA(acc[nt], al, bh[nt]);
            }
        }
        // epilogue: bias + swizzled f32 staging for coalesced scatter
        float* fin = (float*)(smem + FINO);
        const float* bias = (const float*)(smem + BIASO);
        #pragma unroll
        for (int nt = 0; nt < 4; nt++) {
            int c0 = nbase + nt * 8 + 2 * t4, c1 = c0 + 1;
            int tok = mbase + g;
            fin[c0 * 64 + (tok ^ (c0 & 31))] = acc[nt][0] + bias[c0];
            fin[c1 * 64 + (tok ^ (c1 & 31))] = acc[nt][1] + bias[c1];
            fin[c0 * 64 + ((tok + 8) ^ (c0 & 31))] = acc[nt][2] + bias[c0];
            fin[c1 * 64 + ((tok + 8) ^ (c1 & 31))] = acc[nt][3] + bias[c1];
        }
    }
    __syncthreads();

    // ---- phase 4: coalesced scatter with reverse roll ----
    {
        const float* fin = (const float*)(smem + FINO);
        for (int i = tid; i < 64 * 128; i += 512) {
            int c = i >> 6, t = i & 63;
            int h = (hbase + (t >> 3)) & 255;
            int w = (wbase + (t & 7)) & 255;
            out[(((b * 128 + c) * 256) + h) * 256 + w] = fin[c * 64 + (t ^ (c & 31))];
        }
    }
}

extern "C" void kernel_launch(void* const* d_in, const int* in_sizes, int n_in,
                              void* d_out, int out_size)
{
    const float* x      = (const float*)d_in[0];
    const float* w_qkv  = (const float*)d_in[1];
    const float* w_proj = (const float*)d_in[2];
    const float* b_proj = (const float*)d_in[3];
    float* out = (float*)d_out;

    prep_weights<<<256, 256>>>(w_qkv, w_proj);

    cudaFuncSetAttribute(swin_mma3_kernel,
                         cudaFuncAttributeMaxDynamicSharedMemorySize, SMEM_BYTES);
    swin_mma3_kernel<<<8192, 512, SMEM_BYTES>>>(x, b_proj, out);
}

// round 6
// speedup vs baseline: 3.2049x; 1.3623x over previous
#include <cuda_runtime.h>
#include <cuda_bf16.h>
#include <cstdint>

// SwinStyleAttention, mma.sync bf16 hi/lo 3-pass. R6: 8 warps, 32x32 warp tiles
// (170B/MMA vs 256), Q kept entirely in registers (D-frag == A-frag layout),
// conflict-free STS.128 gather, 4-plane cp.async W prefetch. 1 CTA = 1 window.

#define SCALE_ 0.17677669529663687f
#define SWZ(row, colb) (((row) << 8) + ((colb) ^ (((row) & 7) << 4)))

#define XHI   0
#define XLO   16384
#define KHPL  32768
#define KLPL  49152
#define VHPL  65536
#define VLPL  81920
#define PW(i) (98304 + (i) * 32768)
#define BIASO 229376
#define FINO  32768              // f32 [128][64] overlay on K planes (dead by proj)
#define SMEM_BYTES 229888

// swizzled weight plane images: [n*128 + (k ^ ((n&7)<<3))], 16384 bf16 = 32KB each
__device__ __nv_bfloat16 g_wq[3][2][16384];
__device__ __nv_bfloat16 g_wp[2][16384];

static __device__ __forceinline__ uint32_t smem_u32(const void* p) {
    uint32_t a;
    asm("{ .reg .u64 t; cvta.to.shared.u64 t, %1; cvt.u32.u64 %0, t; }" : "=r"(a) : "l"(p));
    return a;
}

#define LDSM4(R0, R1, R2, R3, ADDR) \
    asm volatile("ldmatrix.sync.aligned.m8n8.x4.shared.b16 {%0,%1,%2,%3}, [%4];" \
                 : "=r"(R0), "=r"(R1), "=r"(R2), "=r"(R3) : "r"(ADDR))
#define LDSM4T(R0, R1, R2, R3, ADDR) \
    asm volatile("ldmatrix.sync.aligned.m8n8.x4.trans.shared.b16 {%0,%1,%2,%3}, [%4];" \
                 : "=r"(R0), "=r"(R1), "=r"(R2), "=r"(R3) : "r"(ADDR))
#define MMA(D, A, B) \
    asm volatile("mma.sync.aligned.m16n8k16.row.col.f32.bf16.bf16.f32 " \
                 "{%0,%1,%2,%3},{%4,%5,%6,%7},{%8,%9},{%0,%1,%2,%3};" \
                 : "+f"((D)[0]), "+f"((D)[1]), "+f"((D)[2]), "+f"((D)[3]) \
                 : "r"((A)[0]), "r"((A)[1]), "r"((A)[2]), "r"((A)[3]), \
                   "r"((B)[0]), "r"((B)[1]))
#define CP_ASYNC16(DST, SRC) \
    asm volatile("cp.async.cg.shared.global [%0], [%1], 16;" :: "r"(DST), "l"(SRC))
#define CP_COMMIT() asm volatile("cp.async.commit_group;")
#define CP_WAIT0()  asm volatile("cp.async.wait_group 0;")

static __device__ __forceinline__ void split2(float x, float y, uint32_t& hi, uint32_t& lo) {
    __nv_bfloat16 hx = __float2bfloat16(x), hy = __float2bfloat16(y);
    __nv_bfloat16 lx = __float2bfloat16(x - __bfloat162float(hx));
    __nv_bfloat16 ly = __float2bfloat16(y - __bfloat162float(hy));
    hi = (uint32_t)__bfloat16_as_ushort(hx) | ((uint32_t)__bfloat16_as_ushort(hy) << 16);
    lo = (uint32_t)__bfloat16_as_ushort(lx) | ((uint32_t)__bfloat16_as_ushort(ly) << 16);
}

// ---------------- prep: transpose + hi/lo split weights into swizzled planes --------------
__global__ void prep_weights(const float* __restrict__ wqkv, const float* __restrict__ wproj) {
    int i = blockIdx.x * blockDim.x + threadIdx.x;
    if (i < 49152) {
        int k = i & 127, n = (i >> 7) & 127, nc = i >> 14;
        float v = wqkv[k * 384 + nc * 128 + n];
        __nv_bfloat16 h = __float2bfloat16(v);
        int off = n * 128 + (k ^ ((n & 7) << 3));
        g_wq[nc][0][off] = h;
        g_wq[nc][1][off] = __float2bfloat16(v - __bfloat162float(h));
    } else if (i < 65536) {
        int j = i - 49152;
        int k = j & 127, n = (j >> 7) & 127;
        float v = wproj[k * 128 + n];
        __nv_bfloat16 h = __float2bfloat16(v);
        int off = n * 128 + (k ^ ((n & 7) << 3));
        g_wp[0][off] = h;
        g_wp[1][off] = __float2bfloat16(v - __bfloat162float(h));
    }
}

// ---------------- main fused kernel ----------------
__global__ __launch_bounds__(256, 1)
void swin_mma4_kernel(const float* __restrict__ x,
                      const float* __restrict__ b_proj,
                      float* __restrict__ out)
{
    extern __shared__ __align__(256) unsigned char smem[];
    const uint32_t sb = smem_u32(smem);

    const int tid = threadIdx.x;
    const int lane = tid & 31;
    const int warp = tid >> 5;     // 0..7
    const int g = lane >> 2;
    const int t4 = lane & 3;

    const int win = blockIdx.x;
    const int b = win >> 10, wy = (win >> 5) & 31, wx = win & 31;
    const int hbase = wy * 8 + 4, wbase = wx * 8 + 4;

    auto cpplane = [&](uint32_t dstPlane, const __nv_bfloat16* src) {
        const char* s = (const char*)src;
        #pragma unroll
        for (int i = 0; i < 8; i++) {
            int off = (tid + i * 256) * 16;
            CP_ASYNC16(sb + dstPlane + off, s + off);
        }
        CP_COMMIT();
    };

    // prefetch q + k weights (hi/lo) into P0..P3
    cpplane(PW(0), g_wq[0][0]);
    cpplane(PW(1), g_wq[0][1]);
    cpplane(PW(2), g_wq[1][0]);
    cpplane(PW(3), g_wq[1][1]);

    // ---- phase 0: bias + rolled-window gather; 8 channels/thread, STS.128 conflict-free --
    if (tid < 128) ((float*)(smem + BIASO))[tid] = b_proj[tid];
    #pragma unroll
    for (int it = 0; it < 4; it++) {
        int idx = tid + it * 256;
        int t = idx & 63, cq = idx >> 6;                 // cq: 16 groups of 8 channels
        int h = (hbase + (t >> 3)) & 255;
        int w = (wbase + (t & 7)) & 255;
        const float* xg = x + (size_t)(b * 128 + cq * 8) * 65536 + h * 256 + w;
        uint32_t hp[4], lp[4];
        #pragma unroll
        for (int j = 0; j < 4; j++) {
            float f0 = xg[(size_t)(2 * j) << 16];
            float f1 = xg[(size_t)(2 * j + 1) << 16];
            split2(f0, f1, hp[j], lp[j]);
        }
        *(uint4*)(smem + XHI + SWZ(t, cq * 16)) = make_uint4(hp[0], hp[1], hp[2], hp[3]);
        *(uint4*)(smem + XLO + SWZ(t, cq * 16)) = make_uint4(lp[0], lp[1], lp[2], lp[3]);
    }
    CP_WAIT0();
    __syncthreads();

    const int mbase = (warp >> 2) * 32;   // 2 M tiles of 32 rows
    const int nbase = (warp & 3) * 32;    // 4 N tiles of 32 cols

    float acc[2][4][4];
    // 32x32-tile GEMM: A = X planes (O planes for proj), B = W planes whi/wlo
    auto gemm = [&](uint32_t whi, uint32_t wlo) {
        #pragma unroll
        for (int mf = 0; mf < 2; mf++)
            #pragma unroll
            for (int nt = 0; nt < 4; nt++)
                #pragma unroll
                for (int q = 0; q < 4; q++) acc[mf][nt][q] = 0.f;
        const int arow = mbase + (lane & 15);
        const int brow = nbase + ((lane >> 4) << 3) + (lane & 7);
        #pragma unroll
        for (int kt = 0; kt < 8; kt++) {
            const int acolb = kt * 32 + (lane >> 4) * 16;
            const int bcolb = kt * 32 + ((lane >> 3) & 1) * 16;
            uint32_t ah[2][4], al[2][4], bh[4][2], bl[4][2];
            #pragma unroll
            for (int mf = 0; mf < 2; mf++) {
                LDSM4(ah[mf][0], ah[mf][1], ah[mf][2], ah[mf][3],
                      sb + XHI + SWZ(arow + mf * 16, acolb));
                LDSM4(al[mf][0], al[mf][1], al[mf][2], al[mf][3],
                      sb + XLO + SWZ(arow + mf * 16, acolb));
            }
            #pragma unroll
            for (int ng = 0; ng < 2; ng++) {
                uint32_t r0, r1, r2, r3;
                LDSM4(r0, r1, r2, r3, sb + whi + SWZ(brow + ng * 16, bcolb));
                bh[2 * ng][0] = r0; bh[2 * ng][1] = r1;
                bh[2 * ng + 1][0] = r2; bh[2 * ng + 1][1] = r3;
                LDSM4(r0, r1, r2, r3, sb + wlo + SWZ(brow + ng * 16, bcolb));
                bl[2 * ng][0] = r0; bl[2 * ng][1] = r1;
                bl[2 * ng + 1][0] = r2; bl[2 * ng + 1][1] = r3;
            }
            #pragma unroll
            for (int mf = 0; mf < 2; mf++)
                #pragma unroll
                for (int nt = 0; nt < 4; nt++) {
                    MMA(acc[mf][nt], ah[mf], bh[nt]);
                    MMA(acc[mf][nt], ah[mf], bl[nt]);
                    MMA(acc[mf][nt], al[mf], bh[nt]);
                }
        }
    };
    // epilogue: split acc to hi/lo planes (conflict-free: bank = t4 | g<<2)
    auto store_y = [&](uint32_t yh, uint32_t yl) {
        #pragma unroll
        for (int mf = 0; mf < 2; mf++)
            #pragma unroll
            for (int nt = 0; nt < 4; nt++) {
                int ch = nbase + nt * 8 + 2 * t4;
                int tok = mbase + mf * 16 + g;
                uint32_t hi, lo;
                split2(acc[mf][nt][0], acc[mf][nt][1], hi, lo);
                *(uint32_t*)(smem + yh + SWZ(tok, ch * 2)) = hi;
                *(uint32_t*)(smem + yl + SWZ(tok, ch * 2)) = lo;
                split2(acc[mf][nt][2], acc[mf][nt][3], hi, lo);
                *(uint32_t*)(smem + yh + SWZ(tok + 8, ch * 2)) = hi;
                *(uint32_t*)(smem + yl + SWZ(tok + 8, ch * 2)) = lo;
            }
    };

    // ---- phase 1a: q chunk -> registers only (fold SCALE into hi/lo split) ----
    gemm(PW(0), PW(1));
    uint32_t qfh[2][2][4], qfl[2][2][4];   // [mf][kt(16-chan)][frag]
    #pragma unroll
    for (int mf = 0; mf < 2; mf++)
        #pragma unroll
        for (int kt = 0; kt < 2; kt++) {
            split2(acc[mf][2*kt][0] * SCALE_, acc[mf][2*kt][1] * SCALE_, qfh[mf][kt][0], qfl[mf][kt][0]);
            split2(acc[mf][2*kt][2] * SCALE_, acc[mf][2*kt][3] * SCALE_, qfh[mf][kt][1], qfl[mf][kt][1]);
            split2(acc[mf][2*kt+1][0] * SCALE_, acc[mf][2*kt+1][1] * SCALE_, qfh[mf][kt][2], qfl[mf][kt][2]);
            split2(acc[mf][2*kt+1][2] * SCALE_, acc[mf][2*kt+1][3] * SCALE_, qfh[mf][kt][3], qfl[mf][kt][3]);
        }
    __syncthreads();                       // P0/P1 reads done

    // ---- phase 1b: k chunk (v weights prefetch under it) ----
    cpplane(PW(0), g_wq[2][0]);
    cpplane(PW(1), g_wq[2][1]);
    gemm(PW(2), PW(3));
    store_y(KHPL, KLPL);
    CP_WAIT0();
    __syncthreads();

    // ---- phase 1c: v chunk ----
    gemm(PW(0), PW(1));
    store_y(VHPL, VLPL);
    __syncthreads();                       // V visible; P2/P3 free

    // proj weights prefetch under attention
    cpplane(PW(2), g_wp[0]);
    cpplane(PW(3), g_wp[1]);

    // ---- phase 2: attention; warp = (half = warp>>2, head = warp&3), 32 rows ----
    {
        const int chB = (warp & 3) * 64;   // head's channel byte offset

        float s[2][8][4];
        #pragma unroll
        for (int mf = 0; mf < 2; mf++)
            #pragma unroll
            for (int j = 0; j < 8; j++)
                #pragma unroll
                for (int q = 0; q < 4; q++) s[mf][j][q] = 0.f;

        #pragma unroll
        for (int kt = 0; kt < 2; kt++) {
            const int bcolb = chB + kt * 32 + ((lane >> 3) & 1) * 16;
            #pragma unroll
            for (int ng = 0; ng < 4; ng++) {
                const int brow = ng * 16 + ((lane >> 4) << 3) + (lane & 7);
                uint32_t h0, h1, h2, h3, l0, l1, l2, l3;
                LDSM4(h0, h1, h2, h3, sb + KHPL + SWZ(brow, bcolb));
                LDSM4(l0, l1, l2, l3, sb + KLPL + SWZ(brow, bcolb));
                uint32_t fh0[2] = {h0, h1}, fh1[2] = {h2, h3};
                uint32_t fl0[2] = {l0, l1}, fl1[2] = {l2, l3};
                #pragma unroll
                for (int mf = 0; mf < 2; mf++) {
                    MMA(s[mf][2*ng], qfh[mf][kt], fh0);   MMA(s[mf][2*ng+1], qfh[mf][kt], fh1);
                    MMA(s[mf][2*ng], qfh[mf][kt], fl0);   MMA(s[mf][2*ng+1], qfh[mf][kt], fl1);
                    MMA(s[mf][2*ng], qfl[mf][kt], fh0);   MMA(s[mf][2*ng+1], qfl[mf][kt], fh1);
                }
            }
        }
        // softmax per mf (scale already folded into q)
        float inv0[2], inv1[2];
        #pragma unroll
        for (int mf = 0; mf < 2; mf++) {
            float mx0 = -1e30f, mx1 = -1e30f;
            #pragma unroll
            for (int j = 0; j < 8; j++) {
                mx0 = fmaxf(mx0, fmaxf(s[mf][j][0], s[mf][j][1]));
                mx1 = fmaxf(mx1, fmaxf(s[mf][j][2], s[mf][j][3]));
            }
            mx0 = fmaxf(mx0, __shfl_xor_sync(0xffffffffu, mx0, 1));
            mx0 = fmaxf(mx0, __shfl_xor_sync(0xffffffffu, mx0, 2));
            mx1 = fmaxf(mx1, __shfl_xor_sync(0xffffffffu, mx1, 1));
            mx1 = fmaxf(mx1, __shfl_xor_sync(0xffffffffu, mx1, 2));
            float sm0 = 0.f, sm1 = 0.f;
            #pragma unroll
            for (int j = 0; j < 8; j++) {
                s[mf][j][0] = __expf(s[mf][j][0] - mx0); sm0 += s[mf][j][0];
                s[mf][j][1] = __expf(s[mf][j][1] - mx0); sm0 += s[mf][j][1];
                s[mf][j][2] = __expf(s[mf][j][2] - mx1); sm1 += s[mf][j][2];
                s[mf][j][3] = __expf(s[mf][j][3] - mx1); sm1 += s[mf][j][3];
            }
            sm0 += __shfl_xor_sync(0xffffffffu, sm0, 1);
            sm0 += __shfl_xor_sync(0xffffffffu, sm0, 2);
            sm1 += __shfl_xor_sync(0xffffffffu, sm1, 1);
            sm1 += __shfl_xor_sync(0xffffffffu, sm1, 2);
            inv0[mf] = 1.f / sm0; inv1[mf] = 1.f / sm1;
        }

        // P @ V
        float o[2][4][4];
        #pragma unroll
        for (int mf = 0; mf < 2; mf++)
            #pragma unroll
            for (int nt = 0; nt < 4; nt++)
                #pragma unroll
                for (int q = 0; q < 4; q++) o[mf][nt][q] = 0.f;
        #pragma unroll
        for (int kt = 0; kt < 4; kt++) {
            const int vrow = kt * 16 + (lane & 15);
            uint32_t vh[4][2], vl[4][2];
            #pragma unroll
            for (int ng = 0; ng < 2; ng++) {
                const int vcolb = chB + ng * 32 + (lane >> 4) * 16;
                uint32_t r0, r1, r2, r3;
                LDSM4T(r0, r1, r2, r3, sb + VHPL + SWZ(vrow, vcolb));
                vh[2 * ng][0] = r0; vh[2 * ng][1] = r1;
                vh[2 * ng + 1][0] = r2; vh[2 * ng + 1][1] = r3;
                LDSM4T(r0, r1, r2, r3, sb + VLPL + SWZ(vrow, vcolb));
                vl[2 * ng][0] = r0; vl[2 * ng][1] = r1;
                vl[2 * ng + 1][0] = r2; vl[2 * ng + 1][1] = r3;
            }
            #pragma unroll
            for (int mf = 0; mf < 2; mf++) {
                uint32_t pah[4], pal[4];
                split2(s[mf][2*kt][0] * inv0[mf], s[mf][2*kt][1] * inv0[mf], pah[0], pal[0]);
                split2(s[mf][2*kt][2] * inv1[mf], s[mf][2*kt][3] * inv1[mf], pah[1], pal[1]);
                split2(s[mf][2*kt+1][0] * inv0[mf], s[mf][2*kt+1][1] * inv0[mf], pah[2], pal[2]);
                split2(s[mf][2*kt+1][2] * inv1[mf], s[mf][2*kt+1][3] * inv1[mf], pah[3], pal[3]);
                #pragma unroll
                for (int nt = 0; nt < 4; nt++) {
                    MMA(o[mf][nt], pah, vh[nt]);
                    MMA(o[mf][nt], pah, vl[nt]);
                    MMA(o[mf][nt], pal, vh[nt]);
                }
            }
        }
        // store O (hi/lo) into X planes (x dead)
        #pragma unroll
        for (int mf = 0; mf < 2; mf++)
            #pragma unroll
            for (int nt = 0; nt < 4; nt++) {
                int ch = (warp & 3) * 32 + nt * 8 + 2 * t4;
                int tok = (warp >> 2) * 32 + mf * 16 + g;
                uint32_t hi, lo;
                split2(o[mf][nt][0], o[mf][nt][1], hi, lo);
                *(uint32_t*)(smem + XHI + SWZ(tok, ch * 2)) = hi;
                *(uint32_t*)(smem + XLO + SWZ(tok, ch * 2)) = lo;
                split2(o[mf][nt][2], o[mf][nt][3], hi, lo);
                *(uint32_t*)(smem + XHI + SWZ(tok + 8, ch * 2)) = hi;
                *(uint32_t*)(smem + XLO + SWZ(tok + 8, ch * 2)) = lo;
            }
    }
    CP_WAIT0();
    __syncthreads();

    // ---- phase 3: proj = O @ Wproj + bias ----
    gemm(PW(2), PW(3));
    {
        float* fin = (float*)(smem + FINO);
        const float* bias = (const float*)(smem + BIASO);
        #pragma unroll
        for (int mf = 0; mf < 2; mf++)
            #pragma unroll
            for (int nt = 0; nt < 4; nt++) {
                int c0 = nbase + nt * 8 + 2 * t4, c1 = c0 + 1;
                int tok = mbase + mf * 16 + g;
                fin[c0 * 64 + (tok ^ (c0 & 31))] = acc[mf][nt][0] + bias[c0];
                fin[c1 * 64 + (tok ^ (c1 & 31))] = acc[mf][nt][1] + bias[c1];
                fin[c0 * 64 + ((tok + 8) ^ (c0 & 31))] = acc[mf][nt][2] + bias[c0];
                fin[c1 * 64 + ((tok + 8) ^ (c1 & 31))] = acc[mf][nt][3] + bias[c1];
            }
    }
    __syncthreads();

    // ---- phase 4: coalesced scatter with reverse roll ----
    {
        const float* fin = (const float*)(smem + FINO);
        for (int i = tid; i < 64 * 128; i += 256) {
            int c = i >> 6, t = i & 63;
            int h = (hbase + (t >> 3)) & 255;
            int w = (wbase + (t & 7)) & 255;
            out[(((b * 128 + c) * 256) + h) * 256 + w] = fin[c * 64 + (t ^ (c & 31))];
        }
    }
}

extern "C" void kernel_launch(void* const* d_in, const int* in_sizes, int n_in,
                              void* d_out, int out_size)
{
    const float* x      = (const float*)d_in[0];
    const float* w_qkv  = (const float*)d_in[1];
    const float* w_proj = (const float*)d_in[2];
    const float* b_proj = (const float*)d_in[3];
    float* out = (float*)d_out;

    prep_weights<<<256, 256>>>(w_qkv, w_proj);

    cudaFuncSetAttribute(swin_mma4_kernel,
                         cudaFuncAttributeMaxDynamicSharedMemorySize, SMEM_BYTES);
    swin_mma4_kernel<<<8192, 256, SMEM_BYTES>>>(x, b_proj, out);
}

// round 7
// speedup vs baseline: 3.2575x; 1.0164x over previous
#include <cuda_runtime.h>
#include <cuda_bf16.h>
#include <cstdint>

// SwinStyleAttention, mma.sync bf16 hi/lo 3-pass. R7: R6 + explicit double-buffered
// software pipelining in all MMA loops (gemm kt, QK it, PV kt) + direct global
// proj epilogue (no fin staging). 1 CTA = 1 window, 8 warps, 32x32 warp tiles.

#define SCALE_ 0.17677669529663687f
#define SWZ(row, colb) (((row) << 8) + ((colb) ^ (((row) & 7) << 4)))

#define XHI   0
#define XLO   16384
#define KHPL  32768
#define KLPL  49152
#define VHPL  65536
#define VLPL  81920
#define PW(i) (98304 + (i) * 32768)
#define BIASO 229376
#define SMEM_BYTES 229888

// swizzled weight plane images: [n*128 + (k ^ ((n&7)<<3))], 16384 bf16 = 32KB each
__device__ __nv_bfloat16 g_wq[3][2][16384];
__device__ __nv_bfloat16 g_wp[2][16384];

static __device__ __forceinline__ uint32_t smem_u32(const void* p) {
    uint32_t a;
    asm("{ .reg .u64 t; cvta.to.shared.u64 t, %1; cvt.u32.u64 %0, t; }" : "=r"(a) : "l"(p));
    return a;
}

#define LDSM4(R0, R1, R2, R3, ADDR) \
    asm volatile("ldmatrix.sync.aligned.m8n8.x4.shared.b16 {%0,%1,%2,%3}, [%4];" \
                 : "=r"(R0), "=r"(R1), "=r"(R2), "=r"(R3) : "r"(ADDR))
#define LDSM4T(R0, R1, R2, R3, ADDR) \
    asm volatile("ldmatrix.sync.aligned.m8n8.x4.trans.shared.b16 {%0,%1,%2,%3}, [%4];" \
                 : "=r"(R0), "=r"(R1), "=r"(R2), "=r"(R3) : "r"(ADDR))
#define MMA(D, A, B) \
    asm volatile("mma.sync.aligned.m16n8k16.row.col.f32.bf16.bf16.f32 " \
                 "{%0,%1,%2,%3},{%4,%5,%6,%7},{%8,%9},{%0,%1,%2,%3};" \
                 : "+f"((D)[0]), "+f"((D)[1]), "+f"((D)[2]), "+f"((D)[3]) \
                 : "r"((A)[0]), "r"((A)[1]), "r"((A)[2]), "r"((A)[3]), \
                   "r"((B)[0]), "r"((B)[1]))
#define CP_ASYNC16(DST, SRC) \
    asm volatile("cp.async.cg.shared.global [%0], [%1], 16;" :: "r"(DST), "l"(SRC))
#define CP_COMMIT() asm volatile("cp.async.commit_group;")
#define CP_WAIT0()  asm volatile("cp.async.wait_group 0;")

static __device__ __forceinline__ void split2(float x, float y, uint32_t& hi, uint32_t& lo) {
    __nv_bfloat16 hx = __float2bfloat16(x), hy = __float2bfloat16(y);
    __nv_bfloat16 lx = __float2bfloat16(x - __bfloat162float(hx));
    __nv_bfloat16 ly = __float2bfloat16(y - __bfloat162float(hy));
    hi = (uint32_t)__bfloat16_as_ushort(hx) | ((uint32_t)__bfloat16_as_ushort(hy) << 16);
    lo = (uint32_t)__bfloat16_as_ushort(lx) | ((uint32_t)__bfloat16_as_ushort(ly) << 16);
}

// ---------------- prep: transpose + hi/lo split weights into swizzled planes --------------
__global__ void prep_weights(const float* __restrict__ wqkv, const float* __restrict__ wproj) {
    int i = blockIdx.x * blockDim.x + threadIdx.x;
    if (i < 49152) {
        int k = i & 127, n = (i >> 7) & 127, nc = i >> 14;
        float v = wqkv[k * 384 + nc * 128 + n];
        __nv_bfloat16 h = __float2bfloat16(v);
        int off = n * 128 + (k ^ ((n & 7) << 3));
        g_wq[nc][0][off] = h;
        g_wq[nc][1][off] = __float2bfloat16(v - __bfloat162float(h));
    } else if (i < 65536) {
        int j = i - 49152;
        int k = j & 127, n = (j >> 7) & 127;
        float v = wproj[k * 128 + n];
        __nv_bfloat16 h = __float2bfloat16(v);
        int off = n * 128 + (k ^ ((n & 7) << 3));
        g_wp[0][off] = h;
        g_wp[1][off] = __float2bfloat16(v - __bfloat162float(h));
    }
}

// ---------------- main fused kernel ----------------
__global__ __launch_bounds__(256, 1)
void swin_mma5_kernel(const float* __restrict__ x,
                      const float* __restrict__ b_proj,
                      float* __restrict__ out)
{
    extern __shared__ __align__(256) unsigned char smem[];
    const uint32_t sb = smem_u32(smem);

    const int tid = threadIdx.x;
    const int lane = tid & 31;
    const int warp = tid >> 5;     // 0..7
    const int g = lane >> 2;
    const int t4 = lane & 3;

    const int win = blockIdx.x;
    const int b = win >> 10, wy = (win >> 5) & 31, wx = win & 31;
    const int hbase = wy * 8 + 4, wbase = wx * 8 + 4;

    auto cpplane = [&](uint32_t dstPlane, const __nv_bfloat16* src) {
        const char* s = (const char*)src;
        #pragma unroll
        for (int i = 0; i < 8; i++) {
            int off = (tid + i * 256) * 16;
            CP_ASYNC16(sb + dstPlane + off, s + off);
        }
        CP_COMMIT();
    };

    // prefetch q + k weights (hi/lo) into P0..P3
    cpplane(PW(0), g_wq[0][0]);
    cpplane(PW(1), g_wq[0][1]);
    cpplane(PW(2), g_wq[1][0]);
    cpplane(PW(3), g_wq[1][1]);

    // ---- phase 0: bias + rolled-window gather; 8 channels/thread, STS.128 conflict-free --
    if (tid < 128) ((float*)(smem + BIASO))[tid] = b_proj[tid];
    #pragma unroll
    for (int it = 0; it < 4; it++) {
        int idx = tid + it * 256;
        int t = idx & 63, cq = idx >> 6;                 // cq: 16 groups of 8 channels
        int h = (hbase + (t >> 3)) & 255;
        int w = (wbase + (t & 7)) & 255;
        const float* xg = x + (size_t)(b * 128 + cq * 8) * 65536 + h * 256 + w;
        uint32_t hp[4], lp[4];
        #pragma unroll
        for (int j = 0; j < 4; j++) {
            float f0 = xg[(size_t)(2 * j) << 16];
            float f1 = xg[(size_t)(2 * j + 1) << 16];
            split2(f0, f1, hp[j], lp[j]);
        }
        *(uint4*)(smem + XHI + SWZ(t, cq * 16)) = make_uint4(hp[0], hp[1], hp[2], hp[3]);
        *(uint4*)(smem + XLO + SWZ(t, cq * 16)) = make_uint4(lp[0], lp[1], lp[2], lp[3]);
    }
    CP_WAIT0();
    __syncthreads();

    const int mbase = (warp >> 2) * 32;   // 2 M tiles of 32 rows
    const int nbase = (warp & 3) * 32;    // 4 N tiles of 32 cols

    float acc[2][4][4];
    // 32x32-tile GEMM, double-buffered kt pipeline: prefetch kt+1 frags before MMA(kt)
    auto gemm = [&](uint32_t whi, uint32_t wlo) {
        #pragma unroll
        for (int mf = 0; mf < 2; mf++)
            #pragma unroll
            for (int nt = 0; nt < 4; nt++)
                #pragma unroll
                for (int q = 0; q < 4; q++) acc[mf][nt][q] = 0.f;
        const int arow = mbase + (lane & 15);
        const int brow = nbase + ((lane >> 4) << 3) + (lane & 7);
        uint32_t ah[2][2][4], al[2][2][4], bh[2][4][2], bl[2][4][2];
        auto loadk = [&](int kt, int st) {
            const int acolb = kt * 32 + (lane >> 4) * 16;
            const int bcolb = kt * 32 + ((lane >> 3) & 1) * 16;
            #pragma unroll
            for (int mf = 0; mf < 2; mf++) {
                LDSM4(ah[st][mf][0], ah[st][mf][1], ah[st][mf][2], ah[st][mf][3],
                      sb + XHI + SWZ(arow + mf * 16, acolb));
                LDSM4(al[st][mf][0], al[st][mf][1], al[st][mf][2], al[st][mf][3],
                      sb + XLO + SWZ(arow + mf * 16, acolb));
            }
            #pragma unroll
            for (int ng = 0; ng < 2; ng++) {
                uint32_t r0, r1, r2, r3;
                LDSM4(r0, r1, r2, r3, sb + whi + SWZ(brow + ng * 16, bcolb));
                bh[st][2 * ng][0] = r0; bh[st][2 * ng][1] = r1;
                bh[st][2 * ng + 1][0] = r2; bh[st][2 * ng + 1][1] = r3;
                LDSM4(r0, r1, r2, r3, sb + wlo + SWZ(brow + ng * 16, bcolb));
                bl[st][2 * ng][0] = r0; bl[st][2 * ng][1] = r1;
                bl[st][2 * ng + 1][0] = r2; bl[st][2 * ng + 1][1] = r3;
            }
        };
        loadk(0, 0);
        #pragma unroll
        for (int kt = 0; kt < 8; kt++) {
            const int cur = kt & 1;
            if (kt < 7) loadk(kt + 1, cur ^ 1);
            #pragma unroll
            for (int mf = 0; mf < 2; mf++)
                #pragma unroll
                for (int nt = 0; nt < 4; nt++) {
                    MMA(acc[mf][nt], ah[cur][mf], bh[cur][nt]);
                    MMA(acc[mf][nt], ah[cur][mf], bl[cur][nt]);
                    MMA(acc[mf][nt], al[cur][mf], bh[cur][nt]);
                }
        }
    };
    auto store_y = [&](uint32_t yh, uint32_t yl) {
        #pragma unroll
        for (int mf = 0; mf < 2; mf++)
            #pragma unroll
            for (int nt = 0; nt < 4; nt++) {
                int ch = nbase + nt * 8 + 2 * t4;
                int tok = mbase + mf * 16 + g;
                uint32_t hi, lo;
                split2(acc[mf][nt][0], acc[mf][nt][1], hi, lo);
                *(uint32_t*)(smem + yh + SWZ(tok, ch * 2)) = hi;
                *(uint32_t*)(smem + yl + SWZ(tok, ch * 2)) = lo;
                split2(acc[mf][nt][2], acc[mf][nt][3], hi, lo);
                *(uint32_t*)(smem + yh + SWZ(tok + 8, ch * 2)) = hi;
                *(uint32_t*)(smem + yl + SWZ(tok + 8, ch * 2)) = lo;
            }
    };

    // ---- phase 1a: q chunk -> registers only (fold SCALE into hi/lo split) ----
    gemm(PW(0), PW(1));
    uint32_t qfh[2][2][4], qfl[2][2][4];   // [mf][kt(16-chan)][frag]
    #pragma unroll
    for (int mf = 0; mf < 2; mf++)
        #pragma unroll
        for (int kt = 0; kt < 2; kt++) {
            split2(acc[mf][2*kt][0] * SCALE_, acc[mf][2*kt][1] * SCALE_, qfh[mf][kt][0], qfl[mf][kt][0]);
            split2(acc[mf][2*kt][2] * SCALE_, acc[mf][2*kt][3] * SCALE_, qfh[mf][kt][1], qfl[mf][kt][1]);
            split2(acc[mf][2*kt+1][0] * SCALE_, acc[mf][2*kt+1][1] * SCALE_, qfh[mf][kt][2], qfl[mf][kt][2]);
            split2(acc[mf][2*kt+1][2] * SCALE_, acc[mf][2*kt+1][3] * SCALE_, qfh[mf][kt][3], qfl[mf][kt][3]);
        }
    __syncthreads();                       // P0/P1 reads done

    // ---- phase 1b: k chunk (v weights prefetch under it) ----
    cpplane(PW(0), g_wq[2][0]);
    cpplane(PW(1), g_wq[2][1]);
    gemm(PW(2), PW(3));
    store_y(KHPL, KLPL);
    CP_WAIT0();
    __syncthreads();

    // ---- phase 1c: v chunk ----
    gemm(PW(0), PW(1));
    store_y(VHPL, VLPL);
    __syncthreads();                       // V visible; P2/P3 free

    // proj weights prefetch under attention
    cpplane(PW(2), g_wp[0]);
    cpplane(PW(3), g_wp[1]);

    // ---- phase 2: attention; warp = (half = warp>>2, head = warp&3), 32 rows ----
    {
        const int chB = (warp & 3) * 64;   // head's channel byte offset

        float s[2][8][4];
        #pragma unroll
        for (int mf = 0; mf < 2; mf++)
            #pragma unroll
            for (int j = 0; j < 8; j++)
                #pragma unroll
                for (int q = 0; q < 4; q++) s[mf][j][q] = 0.f;

        // QK^T, pipelined over 8 iterations (kt = it>>2, ng = it&3)
        {
            uint32_t kh[2][4], kl[2][4];
            auto loadK = [&](int it, int st) {
                const int kt = it >> 2, ng = it & 3;
                const int bcolb = chB + kt * 32 + ((lane >> 3) & 1) * 16;
                const int brow = ng * 16 + ((lane >> 4) << 3) + (lane & 7);
                LDSM4(kh[st][0], kh[st][1], kh[st][2], kh[st][3], sb + KHPL + SWZ(brow, bcolb));
                LDSM4(kl[st][0], kl[st][1], kl[st][2], kl[st][3], sb + KLPL + SWZ(brow, bcolb));
            };
            loadK(0, 0);
            #pragma unroll
            for (int it = 0; it < 8; it++) {
                const int cur = it & 1;
                if (it < 7) loadK(it + 1, cur ^ 1);
                const int kt = it >> 2, ng = it & 3;
                #pragma unroll
                for (int mf = 0; mf < 2; mf++) {
                    MMA(s[mf][2*ng],   qfh[mf][kt], kh[cur]);
                    MMA(s[mf][2*ng+1], qfh[mf][kt], kh[cur] + 2);
                    MMA(s[mf][2*ng],   qfh[mf][kt], kl[cur]);
                    MMA(s[mf][2*ng+1], qfh[mf][kt], kl[cur] + 2);
                    MMA(s[mf][2*ng],   qfl[mf][kt], kh[cur]);
                    MMA(s[mf][2*ng+1], qfl[mf][kt], kh[cur] + 2);
                }
            }
        }
        // softmax per mf (scale already folded into q)
        float inv0[2], inv1[2];
        #pragma unroll
        for (int mf = 0; mf < 2; mf++) {
            float mx0 = -1e30f, mx1 = -1e30f;
            #pragma unroll
            for (int j = 0; j < 8; j++) {
                mx0 = fmaxf(mx0, fmaxf(s[mf][j][0], s[mf][j][1]));
                mx1 = fmaxf(mx1, fmaxf(s[mf][j][2], s[mf][j][3]));
            }
            mx0 = fmaxf(mx0, __shfl_xor_sync(0xffffffffu, mx0, 1));
            mx0 = fmaxf(mx0, __shfl_xor_sync(0xffffffffu, mx0, 2));
            mx1 = fmaxf(mx1, __shfl_xor_sync(0xffffffffu, mx1, 1));
            mx1 = fmaxf(mx1, __shfl_xor_sync(0xffffffffu, mx1, 2));
            float sm0 = 0.f, sm1 = 0.f;
            #pragma unroll
            for (int j = 0; j < 8; j++) {
                s[mf][j][0] = __expf(s[mf][j][0] - mx0); sm0 += s[mf][j][0];
                s[mf][j][1] = __expf(s[mf][j][1] - mx0); sm0 += s[mf][j][1];
                s[mf][j][2] = __expf(s[mf][j][2] - mx1); sm1 += s[mf][j][2];
                s[mf][j][3] = __expf(s[mf][j][3] - mx1); sm1 += s[mf][j][3];
            }
            sm0 += __shfl_xor_sync(0xffffffffu, sm0, 1);
            sm0 += __shfl_xor_sync(0xffffffffu, sm0, 2);
            sm1 += __shfl_xor_sync(0xffffffffu, sm1, 1);
            sm1 += __shfl_xor_sync(0xffffffffu, sm1, 2);
            inv0[mf] = 1.f / sm0; inv1[mf] = 1.f / sm1;
        }

        // P @ V, pipelined over kt; P split2 between prefetch and MMAs covers latency
        float o[2][4][4];
        #pragma unroll
        for (int mf = 0; mf < 2; mf++)
            #pragma unroll
            for (int nt = 0; nt < 4; nt++)
                #pragma unroll
                for (int q = 0; q < 4; q++) o[mf][nt][q] = 0.f;
        {
            uint32_t vh[2][4][2], vl[2][4][2];
            auto loadV = [&](int kt, int st) {
                const int vrow = kt * 16 + (lane & 15);
                #pragma unroll
                for (int ng = 0; ng < 2; ng++) {
                    const int vcolb = chB + ng * 32 + (lane >> 4) * 16;
                    uint32_t r0, r1, r2, r3;
                    LDSM4T(r0, r1, r2, r3, sb + VHPL + SWZ(vrow, vcolb));
                    vh[st][2 * ng][0] = r0; vh[st][2 * ng][1] = r1;
                    vh[st][2 * ng + 1][0] = r2; vh[st][2 * ng + 1][1] = r3;
                    LDSM4T(r0, r1, r2, r3, sb + VLPL + SWZ(vrow, vcolb));
                    vl[st][2 * ng][0] = r0; vl[st][2 * ng][1] = r1;
                    vl[st][2 * ng + 1][0] = r2; vl[st][2 * ng + 1][1] = r3;
                }
            };
            loadV(0, 0);
            #pragma unroll
            for (int kt = 0; kt < 4; kt++) {
                const int cur = kt & 1;
                if (kt < 3) loadV(kt + 1, cur ^ 1);
                #pragma unroll
                for (int mf = 0; mf < 2; mf++) {
                    uint32_t pah[4], pal[4];
                    split2(s[mf][2*kt][0] * inv0[mf], s[mf][2*kt][1] * inv0[mf], pah[0], pal[0]);
                    split2(s[mf][2*kt][2] * inv1[mf], s[mf][2*kt][3] * inv1[mf], pah[1], pal[1]);
                    split2(s[mf][2*kt+1][0] * inv0[mf], s[mf][2*kt+1][1] * inv0[mf], pah[2], pal[2]);
                    split2(s[mf][2*kt+1][2] * inv1[mf], s[mf][2*kt+1][3] * inv1[mf], pah[3], pal[3]);
                    #pragma unroll
                    for (int nt = 0; nt < 4; nt++) {
                        MMA(o[mf][nt], pah, vh[cur][nt]);
                        MMA(o[mf][nt], pah, vl[cur][nt]);
                        MMA(o[mf][nt], pal, vh[cur][nt]);
                    }
                }
            }
        }
        // store O (hi/lo) into X planes (x dead)
        #pragma unroll
        for (int mf = 0; mf < 2; mf++)
            #pragma unroll
            for (int nt = 0; nt < 4; nt++) {
                int ch = (warp & 3) * 32 + nt * 8 + 2 * t4;
                int tok = (warp >> 2) * 32 + mf * 16 + g;
                uint32_t hi, lo;
                split2(o[mf][nt][0], o[mf][nt][1], hi, lo);
                *(uint32_t*)(smem + XHI + SWZ(tok, ch * 2)) = hi;
                *(uint32_t*)(smem + XLO + SWZ(tok, ch * 2)) = lo;
                split2(o[mf][nt][2], o[mf][nt][3], hi, lo);
                *(uint32_t*)(smem + XHI + SWZ(tok + 8, ch * 2)) = hi;
                *(uint32_t*)(smem + XLO + SWZ(tok + 8, ch * 2)) = lo;
            }
    }
    CP_WAIT0();
    __syncthreads();

    // ---- phase 3: proj = O @ Wproj + bias; direct global scatter from registers ----
    gemm(PW(2), PW(3));
    {
        const float* bias = (const float*)(smem + BIASO);
        #pragma unroll
        for (int mf = 0; mf < 2; mf++) {
            const int tok0 = mbase + mf * 16 + g;
            const int tok1 = tok0 + 8;
            const int h0 = (hbase + (tok0 >> 3)) & 255, w0 = (wbase + (tok0 & 7)) & 255;
            const int h1 = (hbase + (tok1 >> 3)) & 255, w1 = (wbase + (tok1 & 7)) & 255;
            const size_t p0 = (size_t)h0 * 256 + w0;
            const size_t p1 = (size_t)h1 * 256 + w1;
            #pragma unroll
            for (int nt = 0; nt < 4; nt++) {
                const int c0 = nbase + nt * 8 + 2 * t4, c1 = c0 + 1;
                float* o0 = out + (size_t)(b * 128 + c0) * 65536;
                float* o1 = out + (size_t)(b * 128 + c1) * 65536;
                o0[p0] = acc[mf][nt][0] + bias[c0];
                o1[p0] = acc[mf][nt][1] + bias[c1];
                o0[p1] = acc[mf][nt][2] + bias[c0];
                o1[p1] = acc[mf][nt][3] + bias[c1];
            }
        }
    }
}

extern "C" void kernel_launch(void* const* d_in, const int* in_sizes, int n_in,
                              void* d_out, int out_size)
{
    const float* x      = (const float*)d_in[0];
    const float* w_qkv  = (const float*)d_in[1];
    const float* w_proj = (const float*)d_in[2];
    const float* b_proj = (const float*)d_in[3];
    float* out = (float*)d_out;

    prep_weights<<<256, 256>>>(w_qkv, w_proj);

    cudaFuncSetAttribute(swin_mma5_kernel,
                         cudaFuncAttributeMaxDynamicSharedMemorySize, SMEM_BYTES);
    swin_mma5_kernel<<<8192, 256, SMEM_BYTES>>>(x, b_proj, out);
}